// round 13
// baseline (speedup 1.0000x reference)
#include <cuda_runtime.h>
#include <math.h>

#define TT    16384
#define AA    128
#define KK    128
#define NROW  4
#define NSTEP 16
#define EE    126
#define XSTR  260      // padded xc4 row stride in floats (multiple of 4)
#define CLUSTER 8      // CTAs per row; 16 atoms per CTA; 2048-col shard
#define NTHR  512

typedef unsigned long long u64;

// ---------------- device scratch (static: no allocations allowed) ----------
__device__ __align__(16) float  g_du[AA * KK];
__device__ __align__(16) float  g_xc4[AA * 4 * AA * XSTR]; // ~68MB
__device__ __align__(16) float  g_fm[NROW * AA * TT];
__device__ __align__(16) float  g_res[NROW * TT];
__device__ __align__(16) u64    g_cm64[NROW * TT];   // (fenc(v)<<32)|(127-a)
__device__ __align__(16) float  g_emb[NROW * NSTEP * 128];
__device__ float                g_norm[NROW];
__device__ int                  g_done;

// order-preserving float->uint encoding (monotone bijection)
__device__ __forceinline__ unsigned fenc(float f) {
    unsigned u = __float_as_uint(f);
    return (u & 0x80000000u) ? ~u : (u | 0x80000000u);
}
__device__ __forceinline__ float fdec(unsigned e) {
    return (e & 0x80000000u) ? __uint_as_float(e ^ 0x80000000u)
                             : __uint_as_float(~e);
}

__device__ __forceinline__ unsigned smem_u32(const void* p) {
    return (unsigned)__cvta_generic_to_shared(p);
}
__device__ __forceinline__ unsigned mapa_rank(unsigned addr, int r) {
    unsigned out;
    asm("mapa.shared::cluster.u32 %0, %1, %2;" : "=r"(out) : "r"(addr), "r"(r));
    return out;
}
__device__ __forceinline__ void st_remote_u64(unsigned addr, u64 v) {
    asm volatile("st.shared::cluster.u64 [%0], %1;" :: "r"(addr), "l"(v) : "memory");
}
#define CLUSTER_ARRIVE() asm volatile("barrier.cluster.arrive.aligned;" ::: "memory")
#define CLUSTER_WAIT()   asm volatile("barrier.cluster.wait.aligned;"   ::: "memory")
#define CLUSTER_SYNC() do { CLUSTER_ARRIVE(); CLUSTER_WAIT(); } while (0)

// ---------------- prep: d_unit + residual/cm64 init + xc4 edge zero --------
__global__ void prep_kernel(const float* __restrict__ a,
                            const float* __restrict__ b,
                            const float* __restrict__ d)
{
    __shared__ float sred[4];
    int bx = blockIdx.x;
    int tid = threadIdx.x; // 128
    if (bx == 0 && tid == 0) g_done = 0;
    if (bx < AA) {
        float v = d[bx * KK + tid];
        float ss = v * v;
        #pragma unroll
        for (int off = 16; off; off >>= 1)
            ss += __shfl_down_sync(0xffffffffu, ss, off);
        if ((tid & 31) == 0) sred[tid >> 5] = ss;
        __syncthreads();
        float tot = sred[0] + sred[1] + sred[2] + sred[3];
        g_du[bx * KK + tid] = v / (sqrtf(tot) + 1e-8f);
    } else if (bx < 384) {
        int base = (bx - AA) * 256;
        #pragma unroll
        for (int j = tid; j < 256; j += 128) {
            int i = base + j;
            g_res[i] = (i < 2 * TT) ? a[i] : b[i - 2 * TT];
            g_cm64[i] = 0ull;
        }
    } else {
        int bb = bx - 384;           // 0..511
        int ai = bb >> 2, s = bb & 3;
        int aa2 = tid;
        #pragma unroll
        for (int idx = 0; idx < 4; idx++) {
            int jp = (idx < s) ? idx : 256 + idx;
            g_xc4[((ai * 4 + s) * AA + aa2) * XSTR + jp] = 0.f;
        }
    }
}

// ---------------- correlation kernel, f32x2 (at fp32 FMA floor) ------------
// mode 0: fm (1024 blocks) -> g_fm + g_cm64 (value+argatom)
// mode 1: xcorr (512 blocks) -> g_xc4 via smem staging + coalesced stores
__global__ __launch_bounds__(256) void corr_kernel(int mode)
{
    __shared__ float s_du[KK][64];   // 32KB; reused as 64x128 stage in mode 1
    __shared__ float s_sig[256];
    __shared__ float s_red[8][128];
    __shared__ unsigned char s_reda[8][128];

    int blk = blockIdx.x;
    int tid = threadIdx.x;

    int row, tile, half;
    if (mode == 0) { half = blk & 1; row = (blk >> 1) & 3; tile = blk >> 3; }
    else           { half = blk & 1; tile = (blk >> 1) & 1; row = blk >> 2; }
    int t0 = tile * 128;

    for (int i = tid; i < 64 * KK; i += 256) {
        int al = i >> 7, k = i & 127;
        s_du[k][al] = g_du[(half * 64 + al) * KK + k];
    }

    const float* src;
    int srcLen, shift;
    if (mode == 0) { src = g_res + row * TT; srcLen = TT; shift = 64; }
    else           { src = g_du + row * KK;  srcLen = KK; shift = 127; }

    {
        int t = t0 + tid - shift;
        s_sig[tid] = (t >= 0 && t < srcLen) ? src[t] : 0.f;
    }
    __syncthreads();

    int x = tid & 31, y = tid >> 5;
    int c0 = x * 4, a0 = y * 8;

    u64 acc2[4][4];
    #pragma unroll
    for (int j = 0; j < 4; j++)
        #pragma unroll
        for (int c = 0; c < 4; c++) acc2[j][c] = 0ull;

    unsigned r0 = __float_as_uint(s_sig[c0]);
    unsigned r1 = __float_as_uint(s_sig[c0 + 1]);
    unsigned r2 = __float_as_uint(s_sig[c0 + 2]);
    unsigned r3 = __float_as_uint(s_sig[c0 + 3]);

    #pragma unroll 4
    for (int k = 0; k < KK; k++) {
        u64 dv[4];
        #pragma unroll
        for (int j = 0; j < 4; j++)
            dv[j] = *(const u64*)&s_du[k][a0 + 2 * j];

        u64 rr0, rr1, rr2, rr3;
        asm("mov.b64 %0, {%1, %1};" : "=l"(rr0) : "r"(r0));
        asm("mov.b64 %0, {%1, %1};" : "=l"(rr1) : "r"(r1));
        asm("mov.b64 %0, {%1, %1};" : "=l"(rr2) : "r"(r2));
        asm("mov.b64 %0, {%1, %1};" : "=l"(rr3) : "r"(r3));

        #pragma unroll
        for (int j = 0; j < 4; j++) {
            asm("fma.rn.f32x2 %0, %1, %2, %0;" : "+l"(acc2[j][0]) : "l"(dv[j]), "l"(rr0));
            asm("fma.rn.f32x2 %0, %1, %2, %0;" : "+l"(acc2[j][1]) : "l"(dv[j]), "l"(rr1));
            asm("fma.rn.f32x2 %0, %1, %2, %0;" : "+l"(acc2[j][2]) : "l"(dv[j]), "l"(rr2));
            asm("fma.rn.f32x2 %0, %1, %2, %0;" : "+l"(acc2[j][3]) : "l"(dv[j]), "l"(rr3));
        }
        r0 = r1; r1 = r2; r2 = r3;
        r3 = __float_as_uint(s_sig[c0 + 4 + k]);
    }

    int a_base = half * 64 + a0;
    int t = t0 + c0;

    if (mode == 0) {
        float* out = g_fm + row * AA * TT;
        float cmax[4] = { -3.402823466e38f, -3.402823466e38f,
                          -3.402823466e38f, -3.402823466e38f };
        int carg[4] = { 0, 0, 0, 0 };
        #pragma unroll
        for (int j = 0; j < 4; j++) {
            float lo[4], hi[4];
            #pragma unroll
            for (int c = 0; c < 4; c++) {
                lo[c] = __uint_as_float((unsigned)acc2[j][c]);
                hi[c] = __uint_as_float((unsigned)(acc2[j][c] >> 32));
                if (lo[c] > cmax[c]) { cmax[c] = lo[c]; carg[c] = a_base + 2 * j; }
                if (hi[c] > cmax[c]) { cmax[c] = hi[c]; carg[c] = a_base + 2 * j + 1; }
            }
            *(float4*)(out + (a_base + 2 * j) * TT + t) =
                make_float4(lo[0], lo[1], lo[2], lo[3]);
            *(float4*)(out + (a_base + 2 * j + 1) * TT + t) =
                make_float4(hi[0], hi[1], hi[2], hi[3]);
        }
        #pragma unroll
        for (int c = 0; c < 4; c++) {
            s_red[y][c0 + c] = cmax[c];
            s_reda[y][c0 + c] = (unsigned char)carg[c];
        }
        __syncthreads();
        if (tid < 128) {
            float m = s_red[0][tid];
            int am = s_reda[0][tid];
            #pragma unroll
            for (int w = 1; w < 8; w++) {
                float mw = s_red[w][tid];
                if (mw > m) { m = mw; am = s_reda[w][tid]; }
            }
            u64 key = ((u64)fenc(m) << 32) | (unsigned)(127 - am);
            atomicMax(&g_cm64[row * TT + t0 + tid], key);
        }
    } else {
        // stage 64x128 tile, then coalesced shifted copies
        float* s_stage = &s_du[0][0];
        __syncthreads();
        #pragma unroll
        for (int j = 0; j < 4; j++) {
            float lo[4], hi[4];
            #pragma unroll
            for (int c = 0; c < 4; c++) {
                lo[c] = __uint_as_float((unsigned)acc2[j][c]);
                hi[c] = __uint_as_float((unsigned)(acc2[j][c] >> 32));
            }
            *(float4*)(s_stage + (a0 + 2 * j) * 128 + c0) =
                make_float4(lo[0], lo[1], lo[2], lo[3]);
            *(float4*)(s_stage + (a0 + 2 * j + 1) * 128 + c0) =
                make_float4(hi[0], hi[1], hi[2], hi[3]);
        }
        __syncthreads();

        #pragma unroll
        for (int s = 0; s < 4; s++) {
            int nF4 = (s == 0) ? 32 : 31;
            for (int i = tid; i < 64 * nF4; i += 256) {
                int a = i / nF4, mi = i - a * nF4;
                int localc = (s == 0) ? (4 * mi) : (4 + 4 * mi - s);
                int dstf4  = (s == 0) ? (t0 / 4 + mi) : (t0 / 4 + 1 + mi);
                const float* sp = s_stage + a * 128 + localc;
                float4 v = make_float4(sp[0], sp[1], sp[2], sp[3]);
                long base = ((long)(row * 4 + s) * AA + half * 64 + a) * XSTR;
                *(float4*)(g_xc4 + base + 4 * dstf4) = v;
            }
            if (s > 0) {
                for (int i = tid; i < 64 * 4; i += 256) {
                    int a = i >> 2, q = i & 3;
                    long base = ((long)(row * 4 + s) * AA + half * 64 + a) * XSTR;
                    if (q < 4 - s) {
                        g_xc4[base + t0 + s + q] = s_stage[a * 128 + q];
                    } else {
                        int qq = q - (4 - s);
                        g_xc4[base + t0 + 128 + qq] = s_stage[a * 128 + 128 - s + qq];
                    }
                }
            }
        }
    }
}

// ---------------- steps: 8-CTA cluster, sharded cm, argatom-carrying -------
// smem per CTA:
//   s_cm   [2048 u32]  8192 B   s_ca [2048 u8] 2048 B
//   s_tile [16*XSTR f] 16640 B
//   s_part [8][260] u64 16640 B
//   s_w64  [260 u64]   2080 B
//   s_best [8 u64]     64 B
#define OFF_CA     8192
#define OFF_TILE   10240
#define OFF_PART   26880
#define OFF_W64    43520
#define OFF_BEST   45600
#define SMEM_STEPS 45680

__global__ __launch_bounds__(NTHR, 1) __cluster_dims__(CLUSTER, 1, 1)
void steps_kernel(const float* __restrict__ atom_emb,
                  const float* __restrict__ proj,
                  float* __restrict__ out)
{
    extern __shared__ unsigned char smem_raw[];
    unsigned*      s_cm   = (unsigned*)smem_raw;
    unsigned char* s_ca   = smem_raw + OFF_CA;
    float*         s_tile = (float*)(smem_raw + OFF_TILE);
    u64*           s_part = (u64*)(smem_raw + OFF_PART);   // [src][260]
    u64*           s_w64  = (u64*)(smem_raw + OFF_W64);
    u64*           s_best = (u64*)(smem_raw + OFF_BEST);

    __shared__ u64   s_lb[16];
    __shared__ float s_nred[16];
    __shared__ int   s_last;
    __shared__ float s_keys[64];
    __shared__ int   s_order[64];
    __shared__ float s_proj[128];

    int r    = blockIdx.x / CLUSTER;
    int rank = blockIdx.x % CLUSTER;
    int tid  = threadIdx.x;
    int lane = tid & 31, wid = tid >> 5;
    int my_base = rank * 2048;

    float* fmr  = g_fm  + r * AA * TT;
    float* resr = g_res + r * TT;

    // load owned shard (value + argatom)
    #pragma unroll
    for (int q = 0; q < 4; q++) {
        int i = tid + NTHR * q;
        u64 e = g_cm64[r * TT + my_base + i];
        s_cm[i] = (unsigned)(e >> 32);
        s_ca[i] = (unsigned char)(127 - ((unsigned)e & 0x7Fu));
    }
    __syncthreads();

    // ---- initial candidate: full-shard scan, export to all ranks ----
    {
        uint4 u = ((const uint4*)s_cm)[tid];
        int tb = my_base + tid * 4;
        u64 k  = ((u64)u.x << 14) | (unsigned)(16383 - tb);
        u64 k1 = ((u64)u.y << 14) | (unsigned)(16383 - (tb + 1));
        u64 k2 = ((u64)u.z << 14) | (unsigned)(16383 - (tb + 2));
        u64 k3 = ((u64)u.w << 14) | (unsigned)(16383 - (tb + 3));
        if (k1 > k) k = k1;
        if (k2 > k) k = k2;
        if (k3 > k) k = k3;
        #pragma unroll
        for (int off = 16; off; off >>= 1) {
            u64 o = __shfl_down_sync(0xffffffffu, k, off);
            if (o > k) k = o;
        }
        if (lane == 0) s_lb[wid] = k;
        __syncthreads();
        if (wid == 0) {
            u64 kk = (lane < 16) ? s_lb[lane] : 0ull;
            #pragma unroll
            for (int off = 8; off; off >>= 1) {
                u64 o = __shfl_down_sync(0xffffffffu, kk, off);
                if (o > kk) kk = o;
            }
            if (lane == 0) {
                int tt = 16383 - (int)(kk & 0x3FFFull);
                unsigned venc = (unsigned)(kk >> 14);
                int at = s_ca[tt - my_base];
                u64 cand = ((u64)venc << 21)
                         | ((u64)(unsigned)(16383 - tt) << 7)
                         | (unsigned)(127 - at);
                unsigned loc = smem_u32(&s_best[rank]);
                s_best[rank] = cand;
                #pragma unroll
                for (int d2 = 0; d2 < 8; d2++)
                    if (d2 != rank) st_remote_u64(mapa_rank(loc, d2), cand);
            }
        }
    }

    for (int step = 0; step < NSTEP; step++) {
        CLUSTER_SYNC();     // S1: candidates visible everywhere

        // every thread reduces the 8 candidates locally (broadcast reads)
        u64 best = s_best[0];
        #pragma unroll
        for (int d2 = 1; d2 < 8; d2++) {
            u64 o = s_best[d2];
            if (o > best) best = o;
        }
        int   ti = 16383 - (int)((best >> 7) & 0x3FFFull);
        int   ai = 127 - (int)(best & 0x7Full);
        float v  = fdec((unsigned)(best >> 21));
        int w0   = (ti - 127) & ~3;
        int shf  = (ti - 127) - w0;

        // rank 0: embedding + residual (derived quantities computed locally)
        if (rank == 0 && tid < 128) {
            int pa, aa2;
            if (v > 0.f)      { pa = ti; aa2 = ai; }
            else if (v < 0.f) { pa = (ti == 0) ? 1 : 0; aa2 = (ai == 0) ? 1 : 0; }
            else              { pa = 0; aa2 = 0; }
            float e;
            if (tid == 0)      e = (float)pa * (20.f / (float)(TT - 1));
            else if (tid == 1) e = v;
            else               e = atom_emb[aa2 * EE + (tid - 2)];
            g_emb[(r * NSTEP + step) * 128 + tid] = e;
        } else if (rank == 0 && tid < 256) {
            int k = tid - 128;
            int t = ti - 64 + k;
            if (t >= 0 && t < TT) resr[t] -= v * g_du[ai * KK + k];
        }

        // E: warp wid updates atom rank*16+wid (fm gmem RMW + local tile)
        {
            int a = rank * 16 + wid;
            float*       fp = fmr + a * TT;
            const float* xp = g_xc4 + ((long)(ai * 4 + shf) * AA + a) * XSTR;
            float*       tp = s_tile + wid * XSTR;
            #pragma unroll
            for (int it = 0; it < 3; it++) {
                int jj4 = lane + 32 * it;
                if (jj4 < 65) {
                    int jp = jj4 * 4;
                    int t = w0 + jp;
                    if (t >= 0 && t + 3 < TT) {
                        float4 f = *(const float4*)(fp + t);
                        float4 xx = *(const float4*)(xp + jp);
                        f.x -= v * xx.x; f.y -= v * xx.y;
                        f.z -= v * xx.z; f.w -= v * xx.w;
                        *(float4*)(fp + t) = f;
                        *(float4*)(tp + jp) = f;
                    } else {
                        #pragma unroll
                        for (int e = 0; e < 4; e++) {
                            int te = t + e;
                            if (te >= 0 && te < TT) {
                                float f = fp[te] - v * xp[jp + e];
                                fp[te] = f;
                                tp[jp + e] = f;
                            }
                        }
                    }
                }
            }
        }
        __syncthreads();

        // F: exact (value, atom) window partial; warp w owns quads {w,16+w,32+w,48+w} (+64 for w0)
        {
            int al = lane & 15;
            int ga = rank * 16 + al;             // global atom id
            #pragma unroll
            for (int qi = 0; qi < 5; qi++) {
                int q;
                if (qi < 4) q = wid + 16 * qi;
                else { if (wid != 0) break; q = 64; }
                float4 xx = *(const float4*)(s_tile + al * XSTR + 4 * q);
                u64 k0 = ((u64)fenc(xx.x) << 32) | (unsigned)(127 - ga);
                u64 k1 = ((u64)fenc(xx.y) << 32) | (unsigned)(127 - ga);
                u64 k2 = ((u64)fenc(xx.z) << 32) | (unsigned)(127 - ga);
                u64 k3 = ((u64)fenc(xx.w) << 32) | (unsigned)(127 - ga);
                #pragma unroll
                for (int off = 1; off < 16; off <<= 1) {
                    u64 o0 = __shfl_xor_sync(0xffffffffu, k0, off);
                    u64 o1 = __shfl_xor_sync(0xffffffffu, k1, off);
                    u64 o2 = __shfl_xor_sync(0xffffffffu, k2, off);
                    u64 o3 = __shfl_xor_sync(0xffffffffu, k3, off);
                    if (o0 > k0) k0 = o0;
                    if (o1 > k1) k1 = o1;
                    if (o2 > k2) k2 = o2;
                    if (o3 > k3) k3 = o3;
                }
                if (lane == 0) {
                    s_w64[4 * q]     = k0;
                    s_w64[4 * q + 1] = k1;
                    s_w64[4 * q + 2] = k2;
                    s_w64[4 * q + 3] = k3;
                }
            }
        }
        __syncthreads();

        // G: export window partials to the owner rank of each column
        if (tid < 260) {
            int t = w0 + tid;
            if (t >= 0 && t < TT) {
                int owner = t >> 11;
                u64 val = s_w64[tid];
                unsigned loc = smem_u32(&s_part[rank * 260 + tid]);
                if (owner == rank) s_part[rank * 260 + tid] = val;
                else st_remote_u64(mapa_rank(loc, owner), val);
            }
        }
        CLUSTER_ARRIVE();   // S2 arrive (orders partial exports + fm writes)

        // prescan own shard EXCLUDING current window (hidden under S2 wait)
        u64 preK = 0ull;
        if (step < NSTEP - 1) {
            uint4 u = ((const uint4*)s_cm)[tid];
            int tb = my_base + tid * 4;
            u64 kk[4] = {
                ((u64)u.x << 14) | (unsigned)(16383 - tb),
                ((u64)u.y << 14) | (unsigned)(16383 - (tb + 1)),
                ((u64)u.z << 14) | (unsigned)(16383 - (tb + 2)),
                ((u64)u.w << 14) | (unsigned)(16383 - (tb + 3)) };
            u64 k = 0ull;
            #pragma unroll
            for (int c = 0; c < 4; c++) {
                int t = tb + c;
                bool excl = (t >= w0) && (t < w0 + 260);
                if (!excl && kk[c] > k) k = kk[c];
            }
            #pragma unroll
            for (int off = 16; off; off >>= 1) {
                u64 o = __shfl_down_sync(0xffffffffu, k, off);
                if (o > k) k = o;
            }
            if (lane == 0) s_lb[wid] = k;
            __syncthreads();
            if (wid == 0) {
                u64 k2 = (lane < 16) ? s_lb[lane] : 0ull;
                #pragma unroll
                for (int off = 8; off; off >>= 1) {
                    u64 o = __shfl_down_sync(0xffffffffu, k2, off);
                    if (o > k2) k2 = o;
                }
                preK = k2;   // lane 0 holds it
            }
        }
        CLUSTER_WAIT();     // S2 complete: all partials arrived

        if (step < NSTEP - 1) {
            // fold window partials into owned shard cols
            if (tid < 260) {
                int t = w0 + tid;
                if (t >= 0 && t < TT && (t >> 11) == rank) {
                    u64 m = s_part[tid];
                    #pragma unroll
                    for (int src = 1; src < 8; src++) {
                        u64 mm = s_part[src * 260 + tid];
                        if (mm > m) m = mm;
                    }
                    s_cm[t - my_base] = (unsigned)(m >> 32);
                    s_ca[t - my_base] = (unsigned char)(127 - ((unsigned)m & 0x7Fu));
                }
            }
            __syncthreads();

            // warp 0: scan window cols in own shard, combine, export candidate
            if (wid == 0) {
                u64 k = 0ull;
                #pragma unroll
                for (int ii = 0; ii < 9; ii++) {
                    int i = lane + 32 * ii;
                    if (i < 260) {
                        int t = w0 + i;
                        if (t >= 0 && t < TT && (t >> 11) == rank) {
                            u64 kk2 = ((u64)s_cm[t - my_base] << 14)
                                    | (unsigned)(16383 - t);
                            if (kk2 > k) k = kk2;
                        }
                    }
                }
                #pragma unroll
                for (int off = 16; off; off >>= 1) {
                    u64 o = __shfl_down_sync(0xffffffffu, k, off);
                    if (o > k) k = o;
                }
                if (lane == 0) {
                    if (preK > k) k = preK;
                    int tt = 16383 - (int)(k & 0x3FFFull);
                    unsigned venc = (unsigned)(k >> 14);
                    int at = s_ca[tt - my_base];
                    u64 cand = ((u64)venc << 21)
                             | ((u64)(unsigned)(16383 - tt) << 7)
                             | (unsigned)(127 - at);
                    unsigned loc = smem_u32(&s_best[rank]);
                    s_best[rank] = cand;
                    #pragma unroll
                    for (int d2 = 0; d2 < 8; d2++)
                        if (d2 != rank) st_remote_u64(mapa_rank(loc, d2), cand);
                }
            }
        }
    }

    CLUSTER_SYNC();   // all remote traffic complete; safe to diverge
    if (rank != 0) return;

    // --- residual norm (rank 0) ---
    float ss = 0.f;
    #pragma unroll
    for (int q = 0; q < 8; q++) {
        float4 vv = ((const float4*)resr)[tid + NTHR * q];
        ss += vv.x * vv.x + vv.y * vv.y + vv.z * vv.z + vv.w * vv.w;
    }
    #pragma unroll
    for (int off = 16; off; off >>= 1)
        ss += __shfl_down_sync(0xffffffffu, ss, off);
    if (lane == 0) s_nred[wid] = ss;
    __syncthreads();
    if (wid == 0) {
        float t2 = (lane < 16) ? s_nred[lane] : 0.f;
        #pragma unroll
        for (int off = 8; off; off >>= 1)
            t2 += __shfl_down_sync(0xffffffffu, t2, off);
        if (lane == 0) g_norm[r] = sqrtf(t2);
    }

    // --- fused final loss: last rank-0 to finish computes it ---
    __threadfence();
    __syncthreads();
    if (tid == 0) s_last = (atomicAdd(&g_done, 1) == NROW - 1);
    __syncthreads();
    if (!s_last) return;
    __threadfence();

    if (tid < 128) s_proj[tid] = proj[tid];
    __syncthreads();

    // keys: 16 warps x 4 keys (8 lanes per key)
    {
        int key = wid * 4 + (lane >> 3);
        int sl = lane & 7;
        const float* e = g_emb + key * 128;
        float p = 0.f;
        #pragma unroll
        for (int q = 0; q < 16; q++) {
            int j = sl + 8 * q;
            p += e[j] * s_proj[j];
        }
        #pragma unroll
        for (int off = 1; off < 8; off <<= 1)
            p += __shfl_xor_sync(0xffffffffu, p, off);
        if (sl == 0) s_keys[key] = p;
    }
    __syncthreads();

    if (tid < 4) {   // stable insertion sort, ascending (matches jnp.argsort)
        int ord[16];
        for (int i = 0; i < 16; i++) ord[i] = i;
        for (int i = 1; i < 16; i++) {
            int oi = ord[i];
            float ki = s_keys[tid * 16 + oi];
            int j = i - 1;
            while (j >= 0 && s_keys[tid * 16 + ord[j]] > ki) { ord[j + 1] = ord[j]; j--; }
            ord[j + 1] = oi;
        }
        for (int i = 0; i < 16; i++) s_order[tid * 16 + i] = ord[i];
    }
    __syncthreads();

    float acc = 0.f;
    #pragma unroll
    for (int q = 0; q < 8; q++) {
        int i = tid + NTHR * q;
        int bb = i >> 11;
        int st = (i >> 7) & 15;
        int e = i & 127;
        int sa = s_order[bb * 16 + st];
        int sb = s_order[(2 + bb) * 16 + st];
        float dd = g_emb[(bb * 16 + sa) * 128 + e] - g_emb[((2 + bb) * 16 + sb) * 128 + e];
        acc += dd * dd;
    }
    #pragma unroll
    for (int off = 16; off; off >>= 1)
        acc += __shfl_down_sync(0xffffffffu, acc, off);
    if (lane == 0) s_nred[wid] = acc;
    __syncthreads();
    if (tid == 0) {
        float t2 = 0.f;
        for (int w = 0; w < 16; w++) t2 += s_nred[w];
        out[0] = t2 / 4096.f
               + 0.5f * (fabsf(g_norm[0] - g_norm[2]) + fabsf(g_norm[1] - g_norm[3]));
    }
}

// ---------------- launch ----------------------------------------------------
extern "C" void kernel_launch(void* const* d_in, const int* in_sizes, int n_in,
                              void* d_out, int out_size)
{
    (void)in_sizes; (void)n_in; (void)out_size;
    const float* a    = (const float*)d_in[0];
    const float* b    = (const float*)d_in[1];
    const float* d    = (const float*)d_in[2];
    const float* aemb = (const float*)d_in[3];
    const float* proj = (const float*)d_in[4];
    float* out = (float*)d_out;

    cudaFuncSetAttribute(steps_kernel,
                         cudaFuncAttributeMaxDynamicSharedMemorySize, SMEM_STEPS);

    prep_kernel<<<896, 128>>>(a, b, d);
    corr_kernel<<<512, 256>>>(1);     // xcorr -> g_xc4 (staged, coalesced)
    corr_kernel<<<1024, 256>>>(0);    // fm -> g_fm + g_cm64 (value+argatom)
    steps_kernel<<<NROW * CLUSTER, NTHR, SMEM_STEPS>>>(aemb, proj, out);
}

// round 14
// speedup vs baseline: 1.1322x; 1.1322x over previous
#include <cuda_runtime.h>
#include <math.h>

#define TT    16384
#define AA    128
#define KK    128
#define NROW  4
#define NSTEP 16
#define EE    126
#define XSTR  260      // padded xc4 row stride in floats (multiple of 4)
#define CLUSTER 8      // CTAs per row; 16 atoms per CTA; 2048-col s_cm shard
#define NTHR  512

// ---------------- device scratch (static: no allocations allowed) ----------
__device__ __align__(16) float    g_du[AA * KK];
__device__ __align__(16) float    g_xc4[AA * 4 * AA * XSTR]; // ~68MB
__device__ __align__(16) float    g_fm[NROW * AA * TT];
__device__ __align__(16) float    g_res[NROW * TT];
__device__ __align__(16) unsigned g_cm[NROW * TT];           // encoded colmax
__device__ __align__(16) float    g_emb[NROW * NSTEP * 128];
__device__ float                  g_norm[NROW];
__device__ int                    g_done;

// order-preserving float->uint encoding (monotone bijection)
__device__ __forceinline__ unsigned fenc(float f) {
    unsigned u = __float_as_uint(f);
    return (u & 0x80000000u) ? ~u : (u | 0x80000000u);
}

__device__ __forceinline__ unsigned smem_u32(const void* p) {
    return (unsigned)__cvta_generic_to_shared(p);
}
__device__ __forceinline__ unsigned mapa_rank(unsigned addr, int r) {
    unsigned out;
    asm("mapa.shared::cluster.u32 %0, %1, %2;" : "=r"(out) : "r"(addr), "r"(r));
    return out;
}
__device__ __forceinline__ void st_remote_u32(unsigned addr, unsigned v) {
    asm volatile("st.shared::cluster.u32 [%0], %1;" :: "r"(addr), "r"(v) : "memory");
}
__device__ __forceinline__ void st_remote_u64(unsigned addr, unsigned long long v) {
    asm volatile("st.shared::cluster.u64 [%0], %1;" :: "r"(addr), "l"(v) : "memory");
}
#define CLUSTER_SYNC() do { \
    asm volatile("barrier.cluster.arrive.aligned;" ::: "memory"); \
    asm volatile("barrier.cluster.wait.aligned;"   ::: "memory"); \
} while (0)

// ---------------- prep: d_unit + residual/cm init (384 blocks) -------------
__global__ void prep_kernel(const float* __restrict__ a,
                            const float* __restrict__ b,
                            const float* __restrict__ d)
{
    __shared__ float sred[4];
    int bx = blockIdx.x;
    int tid = threadIdx.x; // 128
    if (bx == 0 && tid == 0) g_done = 0;
    if (bx < AA) {
        float v = d[bx * KK + tid];
        float ss = v * v;
        #pragma unroll
        for (int off = 16; off; off >>= 1)
            ss += __shfl_down_sync(0xffffffffu, ss, off);
        if ((tid & 31) == 0) sred[tid >> 5] = ss;
        __syncthreads();
        float tot = sred[0] + sred[1] + sred[2] + sred[3];
        g_du[bx * KK + tid] = v / (sqrtf(tot) + 1e-8f);
    } else {
        int base = (bx - AA) * 256;
        #pragma unroll
        for (int j = tid; j < 256; j += 128) {
            int i = base + j;
            g_res[i] = (i < 2 * TT) ? a[i] : b[i - 2 * TT];
            g_cm[i] = 0u;
        }
    }
}

// ---------------- merged correlation kernel, f32x2 -------------------------
// blk <  1024 : fm    (row 0..3, tile 0..127, half 0..1) -> g_fm + colmax
// blk >= 1024 : xcorr (row 0..127, tile 0..1, half 0..1) -> g_xc4 (staged,
//               coalesced shifted copies; edge zeroing folded in)
__global__ __launch_bounds__(256) void corr_kernel()
{
    __shared__ float s_du[KK][64];   // 32KB; reused as 64x128 stage in mode 1
    __shared__ float s_sig[256];
    __shared__ float s_red[8][128];

    int blk = blockIdx.x;
    int tid = threadIdx.x;

    int mode, row, tile, half;
    if (blk < 1024) { mode = 0; half = blk & 1; row = (blk >> 1) & 3; tile = blk >> 3; }
    else { int b2 = blk - 1024; mode = 1; half = b2 & 1; tile = (b2 >> 1) & 1; row = b2 >> 2; }
    int t0 = tile * 128;

    for (int i = tid; i < 64 * KK; i += 256) {
        int al = i >> 7, k = i & 127;
        s_du[k][al] = g_du[(half * 64 + al) * KK + k];
    }

    const float* src;
    int srcLen, shift;
    if (mode == 0) { src = g_res + row * TT; srcLen = TT; shift = 64; }
    else           { src = g_du + row * KK;  srcLen = KK; shift = 127; }

    {
        int t = t0 + tid - shift;
        s_sig[tid] = (t >= 0 && t < srcLen) ? src[t] : 0.f;
    }
    __syncthreads();

    int x = tid & 31, y = tid >> 5;
    int c0 = x * 4, a0 = y * 8;

    unsigned long long acc2[4][4];
    #pragma unroll
    for (int j = 0; j < 4; j++)
        #pragma unroll
        for (int c = 0; c < 4; c++) acc2[j][c] = 0ull;

    unsigned r0 = __float_as_uint(s_sig[c0]);
    unsigned r1 = __float_as_uint(s_sig[c0 + 1]);
    unsigned r2 = __float_as_uint(s_sig[c0 + 2]);
    unsigned r3 = __float_as_uint(s_sig[c0 + 3]);

    #pragma unroll 4
    for (int k = 0; k < KK; k++) {
        unsigned long long dv[4];
        #pragma unroll
        for (int j = 0; j < 4; j++)
            dv[j] = *(const unsigned long long*)&s_du[k][a0 + 2 * j];

        unsigned long long rr0, rr1, rr2, rr3;
        asm("mov.b64 %0, {%1, %1};" : "=l"(rr0) : "r"(r0));
        asm("mov.b64 %0, {%1, %1};" : "=l"(rr1) : "r"(r1));
        asm("mov.b64 %0, {%1, %1};" : "=l"(rr2) : "r"(r2));
        asm("mov.b64 %0, {%1, %1};" : "=l"(rr3) : "r"(r3));

        #pragma unroll
        for (int j = 0; j < 4; j++) {
            asm("fma.rn.f32x2 %0, %1, %2, %0;" : "+l"(acc2[j][0]) : "l"(dv[j]), "l"(rr0));
            asm("fma.rn.f32x2 %0, %1, %2, %0;" : "+l"(acc2[j][1]) : "l"(dv[j]), "l"(rr1));
            asm("fma.rn.f32x2 %0, %1, %2, %0;" : "+l"(acc2[j][2]) : "l"(dv[j]), "l"(rr2));
            asm("fma.rn.f32x2 %0, %1, %2, %0;" : "+l"(acc2[j][3]) : "l"(dv[j]), "l"(rr3));
        }
        r0 = r1; r1 = r2; r2 = r3;
        r3 = __float_as_uint(s_sig[c0 + 4 + k]);
    }

    int a_base = half * 64 + a0;
    int t = t0 + c0;

    if (mode == 0) {
        float* out = g_fm + row * AA * TT;
        float cmax[4] = { -3.402823466e38f, -3.402823466e38f,
                          -3.402823466e38f, -3.402823466e38f };
        #pragma unroll
        for (int j = 0; j < 4; j++) {
            float lo[4], hi[4];
            #pragma unroll
            for (int c = 0; c < 4; c++) {
                lo[c] = __uint_as_float((unsigned)acc2[j][c]);
                hi[c] = __uint_as_float((unsigned)(acc2[j][c] >> 32));
                cmax[c] = fmaxf(cmax[c], fmaxf(lo[c], hi[c]));
            }
            *(float4*)(out + (a_base + 2 * j) * TT + t) =
                make_float4(lo[0], lo[1], lo[2], lo[3]);
            *(float4*)(out + (a_base + 2 * j + 1) * TT + t) =
                make_float4(hi[0], hi[1], hi[2], hi[3]);
        }
        #pragma unroll
        for (int c = 0; c < 4; c++) s_red[y][c0 + c] = cmax[c];
        __syncthreads();
        if (tid < 128) {
            float m = s_red[0][tid];
            #pragma unroll
            for (int w = 1; w < 8; w++) m = fmaxf(m, s_red[w][tid]);
            atomicMax(&g_cm[row * TT + t0 + tid], fenc(m));
        }
    } else {
        // stage 64x128 tile, then coalesced shifted copies + edge zeroing
        float* s_stage = &s_du[0][0];
        __syncthreads();
        #pragma unroll
        for (int j = 0; j < 4; j++) {
            float lo[4], hi[4];
            #pragma unroll
            for (int c = 0; c < 4; c++) {
                lo[c] = __uint_as_float((unsigned)acc2[j][c]);
                hi[c] = __uint_as_float((unsigned)(acc2[j][c] >> 32));
            }
            *(float4*)(s_stage + (a0 + 2 * j) * 128 + c0) =
                make_float4(lo[0], lo[1], lo[2], lo[3]);
            *(float4*)(s_stage + (a0 + 2 * j + 1) * 128 + c0) =
                make_float4(hi[0], hi[1], hi[2], hi[3]);
        }
        __syncthreads();

        #pragma unroll
        for (int s = 0; s < 4; s++) {
            int nF4 = (s == 0) ? 32 : 31;
            for (int i = tid; i < 64 * nF4; i += 256) {
                int a = i / nF4, mi = i - a * nF4;
                int localc = (s == 0) ? (4 * mi) : (4 + 4 * mi - s);
                int dstf4  = (s == 0) ? (t0 / 4 + mi) : (t0 / 4 + 1 + mi);
                const float* sp = s_stage + a * 128 + localc;
                float4 v = make_float4(sp[0], sp[1], sp[2], sp[3]);
                long base = ((long)(row * 4 + s) * AA + half * 64 + a) * XSTR;
                *(float4*)(g_xc4 + base + 4 * dstf4) = v;
            }
            if (s > 0) {
                for (int i = tid; i < 64 * 4; i += 256) {
                    int a = i >> 2, q = i & 3;
                    long base = ((long)(row * 4 + s) * AA + half * 64 + a) * XSTR;
                    if (q < 4 - s) {
                        g_xc4[base + t0 + s + q] = s_stage[a * 128 + q];
                    } else {
                        int qq = q - (4 - s);
                        g_xc4[base + t0 + 128 + qq] = s_stage[a * 128 + 128 - s + qq];
                    }
                }
            }
        }

        // edge zeroing (was prep's job): tile0 -> cols [0,s); tile1 -> [256+s,260)
        for (int i = tid; i < 64 * 6; i += 256) {
            int a = i / 6, e = i - (i / 6) * 6;          // e in 0..5
            int s  = (e < 1) ? 1 : (e < 3) ? 2 : 3;      // s=1:1 col, s=2:2, s=3:3
            int q  = (e < 1) ? 0 : (e < 3) ? (e - 1) : (e - 3);
            long base = ((long)(row * 4 + s) * AA + half * 64 + a) * XSTR;
            if (tile == 0) g_xc4[base + q] = 0.f;
            else           g_xc4[base + 256 + s + q] = 0.f;
        }
    }
}

// ---------------- steps: cluster of 8 CTAs per row, SHARDED colmax ---------
// (byte-for-byte the measured-best round-12 version)
#define OFF_TILE   8192
#define OFF_PART   (OFF_TILE + 16 * XSTR * 4)
#define OFF_W      (OFF_PART + 8 * 260 * 4)
#define OFF_BEST   (OFF_W + 260 * 4)
#define SMEM_STEPS (OFF_BEST + 8 * 8 + 16)

__global__ __launch_bounds__(NTHR, 1) __cluster_dims__(CLUSTER, 1, 1)
void steps_kernel(const float* __restrict__ atom_emb,
                  const float* __restrict__ proj,
                  float* __restrict__ out)
{
    extern __shared__ unsigned char smem_raw[];
    unsigned*           s_cm   = (unsigned*)smem_raw;
    float*              s_tile = (float*)(smem_raw + OFF_TILE);
    unsigned*           s_part = (unsigned*)(smem_raw + OFF_PART);  // [src][260]
    unsigned*           s_w    = (unsigned*)(smem_raw + OFF_W);
    unsigned long long* s_best = (unsigned long long*)(smem_raw + OFF_BEST);

    __shared__ unsigned long long s_lb[16];
    __shared__ float s_nred[16];
    __shared__ float sh_v;
    __shared__ int   sh_ti, sh_ai, sh_pa, sh_aa;
    __shared__ int   s_last;
    __shared__ float s_keys[64];
    __shared__ int   s_order[64];
    __shared__ float s_proj[128];

    int r    = blockIdx.x / CLUSTER;
    int rank = blockIdx.x % CLUSTER;
    int tid  = threadIdx.x;
    int lane = tid & 31, wid = tid >> 5;
    int my_base = rank * 2048;

    float* fmr  = g_fm  + r * AA * TT;
    float* resr = g_res + r * TT;

    // load owned colmax shard
    ((uint4*)s_cm)[tid] = ((const uint4*)(g_cm + r * TT + my_base))[tid];
    __syncthreads();

    int prev_w0 = 0;

    for (int step = 0; step < NSTEP; step++) {
        // --- A: owners fold prev-step window partials into owned shard ---
        if (step > 0 && tid < 260) {
            int t = prev_w0 + tid;
            if (t >= 0 && t < TT && (t >> 11) == rank) {
                unsigned m = s_part[tid];
                #pragma unroll
                for (int src = 1; src < 8; src++) {
                    unsigned mm = s_part[src * 260 + tid];
                    if (mm > m) m = mm;
                }
                s_cm[t - my_base] = m;
            }
        }
        __syncthreads();

        // --- B: local argmax over owned 2048 cols; key = (enc<<32)|(~t) ---
        {
            uint4 u = ((const uint4*)s_cm)[tid];
            int tb = my_base + tid * 4;
            unsigned long long k =
                ((unsigned long long)u.x << 32) | (unsigned)(0xFFFFFFFFu - tb);
            unsigned long long k1 =
                ((unsigned long long)u.y << 32) | (unsigned)(0xFFFFFFFFu - (tb + 1));
            unsigned long long k2 =
                ((unsigned long long)u.z << 32) | (unsigned)(0xFFFFFFFFu - (tb + 2));
            unsigned long long k3 =
                ((unsigned long long)u.w << 32) | (unsigned)(0xFFFFFFFFu - (tb + 3));
            if (k1 > k) k = k1;
            if (k2 > k) k = k2;
            if (k3 > k) k = k3;
            #pragma unroll
            for (int off = 16; off; off >>= 1) {
                unsigned long long o = __shfl_down_sync(0xffffffffu, k, off);
                if (o > k) k = o;
            }
            if (lane == 0) s_lb[wid] = k;
        }
        __syncthreads();
        if (wid == 0) {
            unsigned long long k = (lane < 16) ? s_lb[lane] : 0ull;
            #pragma unroll
            for (int off = 8; off; off >>= 1) {
                unsigned long long o = __shfl_down_sync(0xffffffffu, k, off);
                if (o > k) k = o;
            }
            if (lane == 0) {
                unsigned loc = smem_u32(&s_best[rank]);
                s_best[rank] = k;
                #pragma unroll
                for (int d = 0; d < 8; d++)
                    if (d != rank) st_remote_u64(mapa_rank(loc, d), k);
            }
        }
        CLUSTER_SYNC();   // S1: all 8 candidates visible everywhere

        // --- C: global reduce (8 candidates) + atom argmax (warp 0) ---
        if (wid == 0) {
            unsigned long long k = s_best[lane & 7];
            #pragma unroll
            for (int off = 1; off < 8; off <<= 1) {
                unsigned long long o = __shfl_xor_sync(0xffffffffu, k, off);
                if (o > k) k = o;
            }
            int bt = (int)(0xFFFFFFFFu - (unsigned)(k & 0xFFFFFFFFull));

            float av = -3.402823466e38f;
            int aarg = 0x7fffffff;
            #pragma unroll
            for (int a4 = 0; a4 < 4; a4++) {
                int a = lane + 32 * a4;
                float fv = __ldcg(&fmr[a * TT + bt]);
                if (fv > av) { av = fv; aarg = a; }
            }
            #pragma unroll
            for (int off = 16; off; off >>= 1) {
                float ov = __shfl_down_sync(0xffffffffu, av, off);
                int   oa = __shfl_down_sync(0xffffffffu, aarg, off);
                if (ov > av || (ov == av && oa < aarg)) { av = ov; aarg = oa; }
            }
            if (lane == 0) {
                sh_v = av; sh_ti = bt; sh_ai = aarg;
                int pa, aa2;
                if (av > 0.f)      { pa = bt; aa2 = aarg; }
                else if (av < 0.f) { pa = (bt == 0) ? 1 : 0; aa2 = (aarg == 0) ? 1 : 0; }
                else               { pa = 0; aa2 = 0; }
                sh_pa = pa; sh_aa = aa2;
            }
        }
        __syncthreads();

        float v = sh_v;
        int ti = sh_ti, ai = sh_ai;
        int w0  = (ti - 127) & ~3;
        int shf = (ti - 127) - w0;

        // --- D: rank 0 emb + residual; zero s_w (threads 252..511) ---
        if (rank == 0 && tid < 128) {
            float e;
            if (tid == 0)      e = (float)sh_pa * (20.f / (float)(TT - 1));
            else if (tid == 1) e = v;
            else               e = atom_emb[sh_aa * EE + (tid - 2)];
            g_emb[(r * NSTEP + step) * 128 + tid] = e;
        } else if (rank == 0 && tid < 256) {
            int k = tid - 128;
            int t = ti - 64 + k;
            if (t >= 0 && t < TT) resr[t] -= v * g_du[ai * KK + k];
        }
        if (tid >= 252) s_w[tid - 252] = 0u;

        // --- E: phase 3b fm window update; warp wid owns atom rank*16+wid ---
        {
            int a = rank * 16 + wid;
            float*       fp = fmr + a * TT;
            const float* xp = g_xc4 + ((long)(ai * 4 + shf) * AA + a) * XSTR;
            float*       tp = s_tile + wid * XSTR;
            #pragma unroll
            for (int it = 0; it < 3; it++) {
                int jj4 = lane + 32 * it;
                if (jj4 < 65) {
                    int jp = jj4 * 4;
                    int t = w0 + jp;
                    if (t >= 0 && t + 3 < TT) {
                        float4 f = *(const float4*)(fp + t);
                        float4 xx = *(const float4*)(xp + jp);
                        f.x -= v * xx.x; f.y -= v * xx.y;
                        f.z -= v * xx.z; f.w -= v * xx.w;
                        *(float4*)(fp + t) = f;
                        *(float4*)(tp + jp) = f;
                    } else {
                        #pragma unroll
                        for (int e = 0; e < 4; e++) {
                            int te = t + e;
                            if (te >= 0 && te < TT) {
                                float f = fp[te] - v * xp[jp + e];
                                fp[te] = f;
                                tp[jp + e] = f;
                            }
                        }
                    }
                }
            }
        }
        __syncthreads();

        // --- F: local colmax partial over 16 atoms -> s_w ---
        {
            int c4 = tid & 63, sub = tid >> 6;    // 8 subs x 2 atoms
            #pragma unroll
            for (int pass = 0; pass < 2; pass++) {
                int cc4, ss;
                if (pass == 0) { cc4 = c4; ss = sub; }
                else { if (tid >= 8) break; cc4 = 64; ss = tid; }
                float m0 = -3.402823466e38f, m1 = m0, m2 = m0, m3 = m0;
                #pragma unroll
                for (int i = 0; i < 2; i++) {
                    int a = ss * 2 + i;
                    float4 xx = *(const float4*)(s_tile + a * XSTR + 4 * cc4);
                    m0 = fmaxf(m0, xx.x); m1 = fmaxf(m1, xx.y);
                    m2 = fmaxf(m2, xx.z); m3 = fmaxf(m3, xx.w);
                }
                int cb = 4 * cc4;
                atomicMax(&s_w[cb],     fenc(m0));
                atomicMax(&s_w[cb + 1], fenc(m1));
                atomicMax(&s_w[cb + 2], fenc(m2));
                atomicMax(&s_w[cb + 3], fenc(m3));
            }
        }
        __syncthreads();

        // --- G: export partials to the OWNER rank of each window col ---
        if (tid < 260) {
            int t = w0 + tid;
            if (t >= 0 && t < TT) {
                int owner = t >> 11;
                unsigned val = s_w[tid];
                unsigned loc = smem_u32(&s_part[rank * 260 + tid]);
                if (owner == rank) s_part[rank * 260 + tid] = val;
                else st_remote_u32(mapa_rank(loc, owner), val);
            }
        }
        prev_w0 = w0;
        CLUSTER_SYNC();   // S2: partials + fm gmem writes visible
    }

    if (rank != 0) return;   // last cluster op was S2; safe to diverge

    // --- residual norm (rank 0) ---
    float ss = 0.f;
    #pragma unroll
    for (int q = 0; q < 8; q++) {
        float4 vv = ((const float4*)resr)[tid + NTHR * q];
        ss += vv.x * vv.x + vv.y * vv.y + vv.z * vv.z + vv.w * vv.w;
    }
    #pragma unroll
    for (int off = 16; off; off >>= 1)
        ss += __shfl_down_sync(0xffffffffu, ss, off);
    if (lane == 0) s_nred[wid] = ss;
    __syncthreads();
    if (wid == 0) {
        float t2 = (lane < 16) ? s_nred[lane] : 0.f;
        #pragma unroll
        for (int off = 8; off; off >>= 1)
            t2 += __shfl_down_sync(0xffffffffu, t2, off);
        if (lane == 0) g_norm[r] = sqrtf(t2);
    }

    // --- fused final loss: last rank-0 to finish computes it ---
    __threadfence();
    __syncthreads();
    if (tid == 0) s_last = (atomicAdd(&g_done, 1) == NROW - 1);
    __syncthreads();
    if (!s_last) return;
    __threadfence();

    if (tid < 128) s_proj[tid] = proj[tid];
    __syncthreads();

    // keys: 16 warps x 4 keys (8 lanes per key)
    {
        int key = wid * 4 + (lane >> 3);
        int sl = lane & 7;
        const float* e = g_emb + key * 128;
        float p = 0.f;
        #pragma unroll
        for (int q = 0; q < 16; q++) {
            int j = sl + 8 * q;
            p += e[j] * s_proj[j];
        }
        #pragma unroll
        for (int off = 1; off < 8; off <<= 1)
            p += __shfl_xor_sync(0xffffffffu, p, off);
        if (sl == 0) s_keys[key] = p;
    }
    __syncthreads();

    if (tid < 4) {   // stable insertion sort, ascending (matches jnp.argsort)
        int ord[16];
        for (int i = 0; i < 16; i++) ord[i] = i;
        for (int i = 1; i < 16; i++) {
            int oi = ord[i];
            float ki = s_keys[tid * 16 + oi];
            int j = i - 1;
            while (j >= 0 && s_keys[tid * 16 + ord[j]] > ki) { ord[j + 1] = ord[j]; j--; }
            ord[j + 1] = oi;
        }
        for (int i = 0; i < 16; i++) s_order[tid * 16 + i] = ord[i];
    }
    __syncthreads();

    float acc = 0.f;
    #pragma unroll
    for (int q = 0; q < 8; q++) {
        int i = tid + NTHR * q;
        int bb = i >> 11;
        int st = (i >> 7) & 15;
        int e = i & 127;
        int sa = s_order[bb * 16 + st];
        int sb = s_order[(2 + bb) * 16 + st];
        float dd = g_emb[(bb * 16 + sa) * 128 + e] - g_emb[((2 + bb) * 16 + sb) * 128 + e];
        acc += dd * dd;
    }
    #pragma unroll
    for (int off = 16; off; off >>= 1)
        acc += __shfl_down_sync(0xffffffffu, acc, off);
    if (lane == 0) s_nred[wid] = acc;
    __syncthreads();
    if (tid == 0) {
        float t2 = 0.f;
        for (int w = 0; w < 16; w++) t2 += s_nred[w];
        out[0] = t2 / 4096.f
               + 0.5f * (fabsf(g_norm[0] - g_norm[2]) + fabsf(g_norm[1] - g_norm[3]));
    }
}

// ---------------- launch ----------------------------------------------------
extern "C" void kernel_launch(void* const* d_in, const int* in_sizes, int n_in,
                              void* d_out, int out_size)
{
    (void)in_sizes; (void)n_in; (void)out_size;
    const float* a    = (const float*)d_in[0];
    const float* b    = (const float*)d_in[1];
    const float* d    = (const float*)d_in[2];
    const float* aemb = (const float*)d_in[3];
    const float* proj = (const float*)d_in[4];
    float* out = (float*)d_out;

    cudaFuncSetAttribute(steps_kernel,
                         cudaFuncAttributeMaxDynamicSharedMemorySize, SMEM_STEPS);

    prep_kernel<<<384, 128>>>(a, b, d);
    corr_kernel<<<1536, 256>>>();     // fm (1024) + xcorr (512), merged
    steps_kernel<<<NROW * CLUSTER, NTHR, SMEM_STEPS>>>(aemb, proj, out);
}

// round 15
// speedup vs baseline: 1.1670x; 1.0308x over previous
#include <cuda_runtime.h>
#include <math.h>

#define TT    16384
#define AA    128
#define KK    128
#define NROW  4
#define NSTEP 16
#define EE    126
#define XSTR  260      // padded xc4 row stride in floats (multiple of 4)
#define CLUSTER 8      // CTAs per row; 16 atoms per CTA; 2048-col s_cm shard
#define NTHR  512

// ---------------- device scratch (static: no allocations allowed) ----------
__device__ __align__(16) float    g_du[AA * KK];
__device__ __align__(16) float    g_xc4[AA * 4 * AA * XSTR]; // ~68MB
__device__ __align__(16) float    g_fm[NROW * AA * TT];
__device__ __align__(16) float    g_res[NROW * TT];
__device__ __align__(16) unsigned g_cm[NROW * TT];           // encoded colmax
__device__ __align__(16) float    g_emb[NROW * NSTEP * 128];
__device__ float                  g_norm[NROW];
__device__ int                    g_done;

// order-preserving float->uint encoding (monotone bijection)
__device__ __forceinline__ unsigned fenc(float f) {
    unsigned u = __float_as_uint(f);
    return (u & 0x80000000u) ? ~u : (u | 0x80000000u);
}

__device__ __forceinline__ unsigned smem_u32(const void* p) {
    return (unsigned)__cvta_generic_to_shared(p);
}
__device__ __forceinline__ unsigned mapa_rank(unsigned addr, int r) {
    unsigned out;
    asm("mapa.shared::cluster.u32 %0, %1, %2;" : "=r"(out) : "r"(addr), "r"(r));
    return out;
}
__device__ __forceinline__ void st_remote_u32(unsigned addr, unsigned v) {
    asm volatile("st.shared::cluster.u32 [%0], %1;" :: "r"(addr), "r"(v) : "memory");
}
__device__ __forceinline__ void st_remote_u64(unsigned addr, unsigned long long v) {
    asm volatile("st.shared::cluster.u64 [%0], %1;" :: "r"(addr), "l"(v) : "memory");
}
#define CLUSTER_SYNC() do { \
    asm volatile("barrier.cluster.arrive.aligned;" ::: "memory"); \
    asm volatile("barrier.cluster.wait.aligned;"   ::: "memory"); \
} while (0)

// ---------------- prep: d_unit + residual/cm init (384 blocks) -------------
__global__ void prep_kernel(const float* __restrict__ a,
                            const float* __restrict__ b,
                            const float* __restrict__ d)
{
    __shared__ float sred[4];
    int bx = blockIdx.x;
    int tid = threadIdx.x; // 128
    if (bx == 0 && tid == 0) g_done = 0;
    if (bx < AA) {
        float v = d[bx * KK + tid];
        float ss = v * v;
        #pragma unroll
        for (int off = 16; off; off >>= 1)
            ss += __shfl_down_sync(0xffffffffu, ss, off);
        if ((tid & 31) == 0) sred[tid >> 5] = ss;
        __syncthreads();
        float tot = sred[0] + sred[1] + sred[2] + sred[3];
        g_du[bx * KK + tid] = v / (sqrtf(tot) + 1e-8f);
    } else {
        int base = (bx - AA) * 256;
        #pragma unroll
        for (int j = tid; j < 256; j += 128) {
            int i = base + j;
            g_res[i] = (i < 2 * TT) ? a[i] : b[i - 2 * TT];
            g_cm[i] = 0u;
        }
    }
}

// ---------------- correlation kernel, f32x2 (split launches) ---------------
// mode 0 (1024 blocks): fm -> g_fm + colmax
// mode 1 (512 blocks):  xcorr -> g_xc4 (staged, coalesced; edge zeroing folded)
__global__ __launch_bounds__(256) void corr_kernel(int mode)
{
    __shared__ float s_du[KK][64];   // 32KB; reused as 64x128 stage in mode 1
    __shared__ float s_sig[256];
    __shared__ float s_red[8][128];

    int blk = blockIdx.x;
    int tid = threadIdx.x;

    int row, tile, half;
    if (mode == 0) { half = blk & 1; row = (blk >> 1) & 3; tile = blk >> 3; }
    else           { half = blk & 1; tile = (blk >> 1) & 1; row = blk >> 2; }
    int t0 = tile * 128;

    for (int i = tid; i < 64 * KK; i += 256) {
        int al = i >> 7, k = i & 127;
        s_du[k][al] = g_du[(half * 64 + al) * KK + k];
    }

    const float* src;
    int srcLen, shift;
    if (mode == 0) { src = g_res + row * TT; srcLen = TT; shift = 64; }
    else           { src = g_du + row * KK;  srcLen = KK; shift = 127; }

    {
        int t = t0 + tid - shift;
        s_sig[tid] = (t >= 0 && t < srcLen) ? src[t] : 0.f;
    }
    __syncthreads();

    int x = tid & 31, y = tid >> 5;
    int c0 = x * 4, a0 = y * 8;

    unsigned long long acc2[4][4];
    #pragma unroll
    for (int j = 0; j < 4; j++)
        #pragma unroll
        for (int c = 0; c < 4; c++) acc2[j][c] = 0ull;

    unsigned r0 = __float_as_uint(s_sig[c0]);
    unsigned r1 = __float_as_uint(s_sig[c0 + 1]);
    unsigned r2 = __float_as_uint(s_sig[c0 + 2]);
    unsigned r3 = __float_as_uint(s_sig[c0 + 3]);

    #pragma unroll 4
    for (int k = 0; k < KK; k++) {
        unsigned long long dv[4];
        #pragma unroll
        for (int j = 0; j < 4; j++)
            dv[j] = *(const unsigned long long*)&s_du[k][a0 + 2 * j];

        unsigned long long rr0, rr1, rr2, rr3;
        asm("mov.b64 %0, {%1, %1};" : "=l"(rr0) : "r"(r0));
        asm("mov.b64 %0, {%1, %1};" : "=l"(rr1) : "r"(r1));
        asm("mov.b64 %0, {%1, %1};" : "=l"(rr2) : "r"(r2));
        asm("mov.b64 %0, {%1, %1};" : "=l"(rr3) : "r"(r3));

        #pragma unroll
        for (int j = 0; j < 4; j++) {
            asm("fma.rn.f32x2 %0, %1, %2, %0;" : "+l"(acc2[j][0]) : "l"(dv[j]), "l"(rr0));
            asm("fma.rn.f32x2 %0, %1, %2, %0;" : "+l"(acc2[j][1]) : "l"(dv[j]), "l"(rr1));
            asm("fma.rn.f32x2 %0, %1, %2, %0;" : "+l"(acc2[j][2]) : "l"(dv[j]), "l"(rr2));
            asm("fma.rn.f32x2 %0, %1, %2, %0;" : "+l"(acc2[j][3]) : "l"(dv[j]), "l"(rr3));
        }
        r0 = r1; r1 = r2; r2 = r3;
        r3 = __float_as_uint(s_sig[c0 + 4 + k]);
    }

    int a_base = half * 64 + a0;
    int t = t0 + c0;

    if (mode == 0) {
        float* out = g_fm + row * AA * TT;
        float cmax[4] = { -3.402823466e38f, -3.402823466e38f,
                          -3.402823466e38f, -3.402823466e38f };
        #pragma unroll
        for (int j = 0; j < 4; j++) {
            float lo[4], hi[4];
            #pragma unroll
            for (int c = 0; c < 4; c++) {
                lo[c] = __uint_as_float((unsigned)acc2[j][c]);
                hi[c] = __uint_as_float((unsigned)(acc2[j][c] >> 32));
                cmax[c] = fmaxf(cmax[c], fmaxf(lo[c], hi[c]));
            }
            *(float4*)(out + (a_base + 2 * j) * TT + t) =
                make_float4(lo[0], lo[1], lo[2], lo[3]);
            *(float4*)(out + (a_base + 2 * j + 1) * TT + t) =
                make_float4(hi[0], hi[1], hi[2], hi[3]);
        }
        #pragma unroll
        for (int c = 0; c < 4; c++) s_red[y][c0 + c] = cmax[c];
        __syncthreads();
        if (tid < 128) {
            float m = s_red[0][tid];
            #pragma unroll
            for (int w = 1; w < 8; w++) m = fmaxf(m, s_red[w][tid]);
            atomicMax(&g_cm[row * TT + t0 + tid], fenc(m));
        }
    } else {
        // stage 64x128 tile, then coalesced shifted copies + edge zeroing
        float* s_stage = &s_du[0][0];
        __syncthreads();
        #pragma unroll
        for (int j = 0; j < 4; j++) {
            float lo[4], hi[4];
            #pragma unroll
            for (int c = 0; c < 4; c++) {
                lo[c] = __uint_as_float((unsigned)acc2[j][c]);
                hi[c] = __uint_as_float((unsigned)(acc2[j][c] >> 32));
            }
            *(float4*)(s_stage + (a0 + 2 * j) * 128 + c0) =
                make_float4(lo[0], lo[1], lo[2], lo[3]);
            *(float4*)(s_stage + (a0 + 2 * j + 1) * 128 + c0) =
                make_float4(hi[0], hi[1], hi[2], hi[3]);
        }
        __syncthreads();

        #pragma unroll
        for (int s = 0; s < 4; s++) {
            int nF4 = (s == 0) ? 32 : 31;
            for (int i = tid; i < 64 * nF4; i += 256) {
                int a = i / nF4, mi = i - a * nF4;
                int localc = (s == 0) ? (4 * mi) : (4 + 4 * mi - s);
                int dstf4  = (s == 0) ? (t0 / 4 + mi) : (t0 / 4 + 1 + mi);
                const float* sp = s_stage + a * 128 + localc;
                float4 v = make_float4(sp[0], sp[1], sp[2], sp[3]);
                long base = ((long)(row * 4 + s) * AA + half * 64 + a) * XSTR;
                *(float4*)(g_xc4 + base + 4 * dstf4) = v;
            }
            if (s > 0) {
                for (int i = tid; i < 64 * 4; i += 256) {
                    int a = i >> 2, q = i & 3;
                    long base = ((long)(row * 4 + s) * AA + half * 64 + a) * XSTR;
                    if (q < 4 - s) {
                        g_xc4[base + t0 + s + q] = s_stage[a * 128 + q];
                    } else {
                        int qq = q - (4 - s);
                        g_xc4[base + t0 + 128 + qq] = s_stage[a * 128 + 128 - s + qq];
                    }
                }
            }
        }

        // edge zeroing: tile0 -> cols [0,s); tile1 -> [256+s,260)
        for (int i = tid; i < 64 * 6; i += 256) {
            int a = i / 6, e = i - (i / 6) * 6;          // e in 0..5
            int s  = (e < 1) ? 1 : (e < 3) ? 2 : 3;
            int q  = (e < 1) ? 0 : (e < 3) ? (e - 1) : (e - 3);
            long base = ((long)(row * 4 + s) * AA + half * 64 + a) * XSTR;
            if (tile == 0) g_xc4[base + q] = 0.f;
            else           g_xc4[base + 256 + s + q] = 0.f;
        }
    }
}

// ---------------- steps: 8-CTA cluster, sharded colmax, fm preload ---------
#define OFF_TILE   8192
#define OFF_PART   (OFF_TILE + 16 * XSTR * 4)
#define OFF_W      (OFF_PART + 8 * 260 * 4)
#define OFF_BEST   (OFF_W + 260 * 4)
#define SMEM_STEPS (OFF_BEST + 8 * 8 + 16)

__global__ __launch_bounds__(NTHR, 1) __cluster_dims__(CLUSTER, 1, 1)
void steps_kernel(const float* __restrict__ atom_emb,
                  const float* __restrict__ proj,
                  float* __restrict__ out)
{
    extern __shared__ unsigned char smem_raw[];
    unsigned*           s_cm   = (unsigned*)smem_raw;
    float*              s_tile = (float*)(smem_raw + OFF_TILE);
    unsigned*           s_part = (unsigned*)(smem_raw + OFF_PART);  // [src][260]
    unsigned*           s_w    = (unsigned*)(smem_raw + OFF_W);
    unsigned long long* s_best = (unsigned long long*)(smem_raw + OFF_BEST);

    __shared__ unsigned long long s_lb[16];
    __shared__ float s_nred[16];
    __shared__ float sh_v;
    __shared__ int   sh_ai, sh_pa, sh_aa;
    __shared__ int   s_last;
    __shared__ float s_keys[64];
    __shared__ int   s_order[64];
    __shared__ float s_proj[128];

    int r    = blockIdx.x / CLUSTER;
    int rank = blockIdx.x % CLUSTER;
    int tid  = threadIdx.x;
    int lane = tid & 31, wid = tid >> 5;
    int my_base = rank * 2048;

    float* fmr  = g_fm  + r * AA * TT;
    float* resr = g_res + r * TT;

    // load owned colmax shard
    ((uint4*)s_cm)[tid] = ((const uint4*)(g_cm + r * TT + my_base))[tid];
    __syncthreads();

    int prev_w0 = 0;

    for (int step = 0; step < NSTEP; step++) {
        // --- A: owners fold prev-step window partials into owned shard ---
        if (step > 0 && tid < 260) {
            int t = prev_w0 + tid;
            if (t >= 0 && t < TT && (t >> 11) == rank) {
                unsigned m = s_part[tid];
                #pragma unroll
                for (int src = 1; src < 8; src++) {
                    unsigned mm = s_part[src * 260 + tid];
                    if (mm > m) m = mm;
                }
                s_cm[t - my_base] = m;
            }
        }
        __syncthreads();

        // --- B: local argmax over owned 2048 cols; key = (enc<<32)|(~t) ---
        {
            uint4 u = ((const uint4*)s_cm)[tid];
            int tb = my_base + tid * 4;
            unsigned long long k =
                ((unsigned long long)u.x << 32) | (unsigned)(0xFFFFFFFFu - tb);
            unsigned long long k1 =
                ((unsigned long long)u.y << 32) | (unsigned)(0xFFFFFFFFu - (tb + 1));
            unsigned long long k2 =
                ((unsigned long long)u.z << 32) | (unsigned)(0xFFFFFFFFu - (tb + 2));
            unsigned long long k3 =
                ((unsigned long long)u.w << 32) | (unsigned)(0xFFFFFFFFu - (tb + 3));
            if (k1 > k) k = k1;
            if (k2 > k) k = k2;
            if (k3 > k) k = k3;
            #pragma unroll
            for (int off = 16; off; off >>= 1) {
                unsigned long long o = __shfl_down_sync(0xffffffffu, k, off);
                if (o > k) k = o;
            }
            if (lane == 0) s_lb[wid] = k;
        }
        __syncthreads();
        if (wid == 0) {
            unsigned long long k = (lane < 16) ? s_lb[lane] : 0ull;
            #pragma unroll
            for (int off = 8; off; off >>= 1) {
                unsigned long long o = __shfl_down_sync(0xffffffffu, k, off);
                if (o > k) k = o;
            }
            if (lane == 0) {
                unsigned loc = smem_u32(&s_best[rank]);
                s_best[rank] = k;
                #pragma unroll
                for (int d = 0; d < 8; d++)
                    if (d != rank) st_remote_u64(mapa_rank(loc, d), k);
            }
        }
        CLUSTER_SYNC();   // S1: all 8 candidates visible everywhere

        // --- C0: ALL threads compute ti from the 8 candidates -------------
        int ti, w0, shf;
        {
            unsigned long long k = s_best[0];
            #pragma unroll
            for (int d = 1; d < 8; d++) {
                unsigned long long o = s_best[d];
                if (o > k) k = o;
            }
            ti = (int)(0xFFFFFFFFu - (unsigned)(k & 0xFFFFFFFFull));
            w0  = (ti - 127) & ~3;
            shf = (ti - 127) - w0;
        }

        // --- C1: preload own atom's fm window (overlaps warp0's atom scan)
        int a = rank * 16 + wid;
        float* fp = fmr + a * TT;
        float4 fpre[3];
        #pragma unroll
        for (int it = 0; it < 3; it++) {
            int jj4 = lane + 32 * it;
            if (jj4 < 65) {
                int t = w0 + 4 * jj4;
                if (t >= 0 && t + 3 < TT) {
                    fpre[it] = *(const float4*)(fp + t);
                } else {
                    float e0 = (t >= 0 && t < TT)         ? fp[t]     : 0.f;
                    float e1 = (t + 1 >= 0 && t + 1 < TT) ? fp[t + 1] : 0.f;
                    float e2 = (t + 2 >= 0 && t + 2 < TT) ? fp[t + 2] : 0.f;
                    float e3 = (t + 3 >= 0 && t + 3 < TT) ? fp[t + 3] : 0.f;
                    fpre[it] = make_float4(e0, e1, e2, e3);
                }
            }
        }

        // --- C2: warp 0 atom argmax at winning column (gmem, L2-hot) ------
        if (wid == 0) {
            float av = -3.402823466e38f;
            int aarg = 0x7fffffff;
            #pragma unroll
            for (int a4 = 0; a4 < 4; a4++) {
                int aa = lane + 32 * a4;
                float fv = __ldcg(&fmr[aa * TT + ti]);
                if (fv > av) { av = fv; aarg = aa; }
            }
            #pragma unroll
            for (int off = 16; off; off >>= 1) {
                float ov = __shfl_down_sync(0xffffffffu, av, off);
                int   oa = __shfl_down_sync(0xffffffffu, aarg, off);
                if (ov > av || (ov == av && oa < aarg)) { av = ov; aarg = oa; }
            }
            if (lane == 0) {
                sh_v = av; sh_ai = aarg;
                int pa, aa2;
                if (av > 0.f)      { pa = ti; aa2 = aarg; }
                else if (av < 0.f) { pa = (ti == 0) ? 1 : 0; aa2 = (aarg == 0) ? 1 : 0; }
                else               { pa = 0; aa2 = 0; }
                sh_pa = pa; sh_aa = aa2;
            }
        }
        if (tid >= 252) s_w[tid - 252] = 0u;
        __syncthreads();

        float v = sh_v;
        int ai = sh_ai;

        // --- D: rank 0 emb + residual ---
        if (rank == 0 && tid < 128) {
            float e;
            if (tid == 0)      e = (float)sh_pa * (20.f / (float)(TT - 1));
            else if (tid == 1) e = v;
            else               e = atom_emb[sh_aa * EE + (tid - 2)];
            g_emb[(r * NSTEP + step) * 128 + tid] = e;
        } else if (rank == 0 && tid < 256) {
            int k = tid - 128;
            int t = ti - 64 + k;
            if (t >= 0 && t < TT) resr[t] -= v * g_du[ai * KK + k];
        }

        // --- E: window update using preloaded fm values -------------------
        {
            const float* xp = g_xc4 + ((long)(ai * 4 + shf) * AA + a) * XSTR;
            float*       tp = s_tile + wid * XSTR;
            #pragma unroll
            for (int it = 0; it < 3; it++) {
                int jj4 = lane + 32 * it;
                if (jj4 < 65) {
                    int jp = 4 * jj4;
                    int t = w0 + jp;
                    float4 xx = *(const float4*)(xp + jp);
                    float4 f = fpre[it];
                    f.x -= v * xx.x; f.y -= v * xx.y;
                    f.z -= v * xx.z; f.w -= v * xx.w;
                    if (t >= 0 && t + 3 < TT) {
                        *(float4*)(fp + t) = f;
                        *(float4*)(tp + jp) = f;
                    } else {
                        if (t >= 0 && t < TT)         { fp[t]     = f.x; tp[jp]     = f.x; }
                        if (t + 1 >= 0 && t + 1 < TT) { fp[t + 1] = f.y; tp[jp + 1] = f.y; }
                        if (t + 2 >= 0 && t + 2 < TT) { fp[t + 2] = f.z; tp[jp + 2] = f.z; }
                        if (t + 3 >= 0 && t + 3 < TT) { fp[t + 3] = f.w; tp[jp + 3] = f.w; }
                    }
                }
            }
        }
        __syncthreads();

        // --- F: local colmax partial over 16 atoms -> s_w ---
        {
            int c4 = tid & 63, sub = tid >> 6;    // 8 subs x 2 atoms
            #pragma unroll
            for (int pass = 0; pass < 2; pass++) {
                int cc4, ss;
                if (pass == 0) { cc4 = c4; ss = sub; }
                else { if (tid >= 8) break; cc4 = 64; ss = tid; }
                float m0 = -3.402823466e38f, m1 = m0, m2 = m0, m3 = m0;
                #pragma unroll
                for (int i = 0; i < 2; i++) {
                    int aa = ss * 2 + i;
                    float4 xx = *(const float4*)(s_tile + aa * XSTR + 4 * cc4);
                    m0 = fmaxf(m0, xx.x); m1 = fmaxf(m1, xx.y);
                    m2 = fmaxf(m2, xx.z); m3 = fmaxf(m3, xx.w);
                }
                int cb = 4 * cc4;
                atomicMax(&s_w[cb],     fenc(m0));
                atomicMax(&s_w[cb + 1], fenc(m1));
                atomicMax(&s_w[cb + 2], fenc(m2));
                atomicMax(&s_w[cb + 3], fenc(m3));
            }
        }
        __syncthreads();

        // --- G: export partials to the OWNER rank of each window col ---
        if (tid < 260) {
            int t = w0 + tid;
            if (t >= 0 && t < TT) {
                int owner = t >> 11;
                unsigned val = s_w[tid];
                unsigned loc = smem_u32(&s_part[rank * 260 + tid]);
                if (owner == rank) s_part[rank * 260 + tid] = val;
                else st_remote_u32(mapa_rank(loc, owner), val);
            }
        }
        prev_w0 = w0;
        CLUSTER_SYNC();   // S2: partials + fm gmem writes visible
    }

    if (rank != 0) return;   // last cluster op was S2; safe to diverge

    // --- residual norm (rank 0) ---
    float ss = 0.f;
    #pragma unroll
    for (int q = 0; q < 8; q++) {
        float4 vv = ((const float4*)resr)[tid + NTHR * q];
        ss += vv.x * vv.x + vv.y * vv.y + vv.z * vv.z + vv.w * vv.w;
    }
    #pragma unroll
    for (int off = 16; off; off >>= 1)
        ss += __shfl_down_sync(0xffffffffu, ss, off);
    if (lane == 0) s_nred[wid] = ss;
    __syncthreads();
    if (wid == 0) {
        float t2 = (lane < 16) ? s_nred[lane] : 0.f;
        #pragma unroll
        for (int off = 8; off; off >>= 1)
            t2 += __shfl_down_sync(0xffffffffu, t2, off);
        if (lane == 0) g_norm[r] = sqrtf(t2);
    }

    // --- fused final loss: last rank-0 to finish computes it ---
    __threadfence();
    __syncthreads();
    if (tid == 0) s_last = (atomicAdd(&g_done, 1) == NROW - 1);
    __syncthreads();
    if (!s_last) return;
    __threadfence();

    if (tid < 128) s_proj[tid] = proj[tid];
    __syncthreads();

    // keys: 16 warps x 4 keys (8 lanes per key)
    {
        int key = wid * 4 + (lane >> 3);
        int sl = lane & 7;
        const float* e = g_emb + key * 128;
        float p = 0.f;
        #pragma unroll
        for (int q = 0; q < 16; q++) {
            int j = sl + 8 * q;
            p += e[j] * s_proj[j];
        }
        #pragma unroll
        for (int off = 1; off < 8; off <<= 1)
            p += __shfl_xor_sync(0xffffffffu, p, off);
        if (sl == 0) s_keys[key] = p;
    }
    __syncthreads();

    if (tid < 4) {   // stable insertion sort, ascending (matches jnp.argsort)
        int ord[16];
        for (int i = 0; i < 16; i++) ord[i] = i;
        for (int i = 1; i < 16; i++) {
            int oi = ord[i];
            float ki = s_keys[tid * 16 + oi];
            int j = i - 1;
            while (j >= 0 && s_keys[tid * 16 + ord[j]] > ki) { ord[j + 1] = ord[j]; j--; }
            ord[j + 1] = oi;
        }
        for (int i = 0; i < 16; i++) s_order[tid * 16 + i] = ord[i];
    }
    __syncthreads();

    float acc = 0.f;
    #pragma unroll
    for (int q = 0; q < 8; q++) {
        int i = tid + NTHR * q;
        int bb = i >> 11;
        int st = (i >> 7) & 15;
        int e = i & 127;
        int sa = s_order[bb * 16 + st];
        int sb = s_order[(2 + bb) * 16 + st];
        float dd = g_emb[(bb * 16 + sa) * 128 + e] - g_emb[((2 + bb) * 16 + sb) * 128 + e];
        acc += dd * dd;
    }
    #pragma unroll
    for (int off = 16; off; off >>= 1)
        acc += __shfl_down_sync(0xffffffffu, acc, off);
    if (lane == 0) s_nred[wid] = acc;
    __syncthreads();
    if (tid == 0) {
        float t2 = 0.f;
        for (int w = 0; w < 16; w++) t2 += s_nred[w];
        out[0] = t2 / 4096.f
               + 0.5f * (fabsf(g_norm[0] - g_norm[2]) + fabsf(g_norm[1] - g_norm[3]));
    }
}

// ---------------- launch ----------------------------------------------------
extern "C" void kernel_launch(void* const* d_in, const int* in_sizes, int n_in,
                              void* d_out, int out_size)
{
    (void)in_sizes; (void)n_in; (void)out_size;
    const float* a    = (const float*)d_in[0];
    const float* b    = (const float*)d_in[1];
    const float* d    = (const float*)d_in[2];
    const float* aemb = (const float*)d_in[3];
    const float* proj = (const float*)d_in[4];
    float* out = (float*)d_out;

    cudaFuncSetAttribute(steps_kernel,
                         cudaFuncAttributeMaxDynamicSharedMemorySize, SMEM_STEPS);

    prep_kernel<<<384, 128>>>(a, b, d);
    corr_kernel<<<512, 256>>>(1);     // xcorr -> g_xc4 (staged, coalesced)
    corr_kernel<<<1024, 256>>>(0);    // fm -> g_fm + g_cm
    steps_kernel<<<NROW * CLUSTER, NTHR, SMEM_STEPS>>>(aemb, proj, out);
}

// round 17
// speedup vs baseline: 1.2662x; 1.0850x over previous
#include <cuda_runtime.h>
#include <math.h>

#define TT    16384
#define AA    128
#define KK    128
#define NROW  4
#define NSTEP 16
#define EE    126
#define XSTR  260      // s_tile row stride in floats (bank-friendly)
#define XCL   256      // xc row length (single copy, j in [0,255])
#define CLUSTER 8
#define NTHR  512

// ---------------- device scratch (static: no allocations allowed) ----------
__device__ __align__(16) float    g_du[AA * KK];
__device__ __align__(16) float    g_xc[AA * AA * XCL];      // 16.8MB single copy
__device__ __align__(16) float    g_fm[NROW * AA * TT];
__device__ __align__(16) float    g_res[NROW * TT];
__device__ __align__(16) unsigned g_cm[NROW * TT];          // encoded colmax
__device__ __align__(16) float    g_emb[NROW * NSTEP * 128];
__device__ float                  g_norm[NROW];
__device__ int                    g_done;

// order-preserving float->uint encoding (monotone bijection)
__device__ __forceinline__ unsigned fenc(float f) {
    unsigned u = __float_as_uint(f);
    return (u & 0x80000000u) ? ~u : (u | 0x80000000u);
}

__device__ __forceinline__ unsigned smem_u32(const void* p) {
    return (unsigned)__cvta_generic_to_shared(p);
}
__device__ __forceinline__ unsigned mapa_rank(unsigned addr, int r) {
    unsigned out;
    asm("mapa.shared::cluster.u32 %0, %1, %2;" : "=r"(out) : "r"(addr), "r"(r));
    return out;
}
__device__ __forceinline__ void st_remote_u32(unsigned addr, unsigned v) {
    asm volatile("st.shared::cluster.u32 [%0], %1;" :: "r"(addr), "r"(v) : "memory");
}
__device__ __forceinline__ void st_remote_u64(unsigned addr, unsigned long long v) {
    asm volatile("st.shared::cluster.u64 [%0], %1;" :: "r"(addr), "l"(v) : "memory");
}
#define CLUSTER_SYNC() do { \
    asm volatile("barrier.cluster.arrive.aligned;" ::: "memory"); \
    asm volatile("barrier.cluster.wait.aligned;"   ::: "memory"); \
} while (0)

// ---------------- prep: d_unit + residual/cm init (384 blocks) -------------
__global__ void prep_kernel(const float* __restrict__ a,
                            const float* __restrict__ b,
                            const float* __restrict__ d)
{
    __shared__ float sred[4];
    int bx = blockIdx.x;
    int tid = threadIdx.x; // 128
    if (bx == 0 && tid == 0) g_done = 0;
    if (bx < AA) {
        float v = d[bx * KK + tid];
        float ss = v * v;
        #pragma unroll
        for (int off = 16; off; off >>= 1)
            ss += __shfl_down_sync(0xffffffffu, ss, off);
        if ((tid & 31) == 0) sred[tid >> 5] = ss;
        __syncthreads();
        float tot = sred[0] + sred[1] + sred[2] + sred[3];
        g_du[bx * KK + tid] = v / (sqrtf(tot) + 1e-8f);
    } else {
        int base = (bx - AA) * 256;
        #pragma unroll
        for (int j = tid; j < 256; j += 128) {
            int i = base + j;
            g_res[i] = (i < 2 * TT) ? a[i] : b[i - 2 * TT];
            g_cm[i] = 0u;
        }
    }
}

// ---------------- correlation kernel, f32x2 (split launches) ---------------
// mode 0 (1024 blocks): fm -> g_fm + colmax
// mode 1 (512 blocks):  xcorr -> g_xc (single copy, direct strided stores)
__global__ __launch_bounds__(256) void corr_kernel(int mode)
{
    __shared__ float s_du[KK][64];   // [k][a_local] 32KB
    __shared__ float s_sig[256];
    __shared__ float s_red[8][128];

    int blk = blockIdx.x;
    int tid = threadIdx.x;

    int row, tile, half;
    if (mode == 0) { half = blk & 1; row = (blk >> 1) & 3; tile = blk >> 3; }
    else           { half = blk & 1; tile = (blk >> 1) & 1; row = blk >> 2; }
    int t0 = tile * 128;

    for (int i = tid; i < 64 * KK; i += 256) {
        int al = i >> 7, k = i & 127;
        s_du[k][al] = g_du[(half * 64 + al) * KK + k];
    }

    const float* src;
    int srcLen, shift;
    if (mode == 0) { src = g_res + row * TT; srcLen = TT; shift = 64; }
    else           { src = g_du + row * KK;  srcLen = KK; shift = 127; }

    {
        int t = t0 + tid - shift;
        s_sig[tid] = (t >= 0 && t < srcLen) ? src[t] : 0.f;
    }
    __syncthreads();

    int x = tid & 31, y = tid >> 5;
    int c0 = x * 4, a0 = y * 8;

    unsigned long long acc2[4][4];
    #pragma unroll
    for (int j = 0; j < 4; j++)
        #pragma unroll
        for (int c = 0; c < 4; c++) acc2[j][c] = 0ull;

    unsigned r0 = __float_as_uint(s_sig[c0]);
    unsigned r1 = __float_as_uint(s_sig[c0 + 1]);
    unsigned r2 = __float_as_uint(s_sig[c0 + 2]);
    unsigned r3 = __float_as_uint(s_sig[c0 + 3]);

    #pragma unroll 4
    for (int k = 0; k < KK; k++) {
        unsigned long long dv[4];
        #pragma unroll
        for (int j = 0; j < 4; j++)
            dv[j] = *(const unsigned long long*)&s_du[k][a0 + 2 * j];

        unsigned long long rr0, rr1, rr2, rr3;
        asm("mov.b64 %0, {%1, %1};" : "=l"(rr0) : "r"(r0));
        asm("mov.b64 %0, {%1, %1};" : "=l"(rr1) : "r"(r1));
        asm("mov.b64 %0, {%1, %1};" : "=l"(rr2) : "r"(r2));
        asm("mov.b64 %0, {%1, %1};" : "=l"(rr3) : "r"(r3));

        #pragma unroll
        for (int j = 0; j < 4; j++) {
            asm("fma.rn.f32x2 %0, %1, %2, %0;" : "+l"(acc2[j][0]) : "l"(dv[j]), "l"(rr0));
            asm("fma.rn.f32x2 %0, %1, %2, %0;" : "+l"(acc2[j][1]) : "l"(dv[j]), "l"(rr1));
            asm("fma.rn.f32x2 %0, %1, %2, %0;" : "+l"(acc2[j][2]) : "l"(dv[j]), "l"(rr2));
            asm("fma.rn.f32x2 %0, %1, %2, %0;" : "+l"(acc2[j][3]) : "l"(dv[j]), "l"(rr3));
        }
        r0 = r1; r1 = r2; r2 = r3;
        r3 = __float_as_uint(s_sig[c0 + 4 + k]);
    }

    int a_base = half * 64 + a0;
    int t = t0 + c0;

    if (mode == 0) {
        float* out = g_fm + row * AA * TT;
        float cmax[4] = { -3.402823466e38f, -3.402823466e38f,
                          -3.402823466e38f, -3.402823466e38f };
        #pragma unroll
        for (int j = 0; j < 4; j++) {
            float lo[4], hi[4];
            #pragma unroll
            for (int c = 0; c < 4; c++) {
                lo[c] = __uint_as_float((unsigned)acc2[j][c]);
                hi[c] = __uint_as_float((unsigned)(acc2[j][c] >> 32));
                cmax[c] = fmaxf(cmax[c], fmaxf(lo[c], hi[c]));
            }
            *(float4*)(out + (a_base + 2 * j) * TT + t) =
                make_float4(lo[0], lo[1], lo[2], lo[3]);
            *(float4*)(out + (a_base + 2 * j + 1) * TT + t) =
                make_float4(hi[0], hi[1], hi[2], hi[3]);
        }
        #pragma unroll
        for (int c = 0; c < 4; c++) s_red[y][c0 + c] = cmax[c];
        __syncthreads();
        if (tid < 128) {
            float m = s_red[0][tid];
            #pragma unroll
            for (int w = 1; w < 8; w++) m = fmaxf(m, s_red[w][tid]);
            atomicMax(&g_cm[row * TT + t0 + tid], fenc(m));
        }
    } else {
        // single-copy xc: direct strided float4 stores (same shape as mode 0)
        float* out = g_xc + (long)row * AA * XCL;
        #pragma unroll
        for (int j = 0; j < 4; j++) {
            float lo[4], hi[4];
            #pragma unroll
            for (int c = 0; c < 4; c++) {
                lo[c] = __uint_as_float((unsigned)acc2[j][c]);
                hi[c] = __uint_as_float((unsigned)(acc2[j][c] >> 32));
            }
            *(float4*)(out + (a_base + 2 * j) * XCL + t) =
                make_float4(lo[0], lo[1], lo[2], lo[3]);
            *(float4*)(out + (a_base + 2 * j + 1) * XCL + t) =
                make_float4(hi[0], hi[1], hi[2], hi[3]);
        }
    }
}

// ---------------- steps: 8-CTA cluster, sharded colmax, fm preload ---------
#define OFF_TILE   8192
#define OFF_PART   (OFF_TILE + 16 * XSTR * 4)
#define OFF_W      (OFF_PART + 8 * 260 * 4)
#define OFF_BEST   (OFF_W + 260 * 4)
#define SMEM_STEPS (OFF_BEST + 8 * 8 + 16)

__global__ __launch_bounds__(NTHR, 1) __cluster_dims__(CLUSTER, 1, 1)
void steps_kernel(const float* __restrict__ atom_emb,
                  const float* __restrict__ proj,
                  float* __restrict__ out)
{
    extern __shared__ unsigned char smem_raw[];
    unsigned*           s_cm   = (unsigned*)smem_raw;
    float*              s_tile = (float*)(smem_raw + OFF_TILE);
    unsigned*           s_part = (unsigned*)(smem_raw + OFF_PART);  // [src][260]
    unsigned*           s_w    = (unsigned*)(smem_raw + OFF_W);
    unsigned long long* s_best = (unsigned long long*)(smem_raw + OFF_BEST);

    __shared__ unsigned long long s_lb[16];
    __shared__ float s_nred[16];
    __shared__ float sh_v;
    __shared__ int   sh_ai, sh_pa, sh_aa;
    __shared__ int   s_last;
    __shared__ float s_keys[64];
    __shared__ int   s_order[64];
    __shared__ float s_proj[128];

    int r    = blockIdx.x / CLUSTER;
    int rank = blockIdx.x % CLUSTER;
    int tid  = threadIdx.x;
    int lane = tid & 31, wid = tid >> 5;
    int my_base = rank * 2048;

    float* fmr  = g_fm  + r * AA * TT;
    float* resr = g_res + r * TT;

    // load owned colmax shard
    ((uint4*)s_cm)[tid] = ((const uint4*)(g_cm + r * TT + my_base))[tid];
    __syncthreads();

    int prev_w0 = 0;

    for (int step = 0; step < NSTEP; step++) {
        // --- A: owners fold prev-step window partials into owned shard ---
        if (step > 0 && tid < 260) {
            int t = prev_w0 + tid;
            if (t >= 0 && t < TT && (t >> 11) == rank) {
                unsigned m = s_part[tid];
                #pragma unroll
                for (int src = 1; src < 8; src++) {
                    unsigned mm = s_part[src * 260 + tid];
                    if (mm > m) m = mm;
                }
                s_cm[t - my_base] = m;
            }
        }
        __syncthreads();

        // --- B: local argmax over owned 2048 cols; key = (enc<<32)|(~t) ---
        {
            uint4 u = ((const uint4*)s_cm)[tid];
            int tb = my_base + tid * 4;
            unsigned long long k =
                ((unsigned long long)u.x << 32) | (unsigned)(0xFFFFFFFFu - tb);
            unsigned long long k1 =
                ((unsigned long long)u.y << 32) | (unsigned)(0xFFFFFFFFu - (tb + 1));
            unsigned long long k2 =
                ((unsigned long long)u.z << 32) | (unsigned)(0xFFFFFFFFu - (tb + 2));
            unsigned long long k3 =
                ((unsigned long long)u.w << 32) | (unsigned)(0xFFFFFFFFu - (tb + 3));
            if (k1 > k) k = k1;
            if (k2 > k) k = k2;
            if (k3 > k) k = k3;
            #pragma unroll
            for (int off = 16; off; off >>= 1) {
                unsigned long long o = __shfl_down_sync(0xffffffffu, k, off);
                if (o > k) k = o;
            }
            if (lane == 0) s_lb[wid] = k;
        }
        __syncthreads();
        if (wid == 0) {
            unsigned long long k = (lane < 16) ? s_lb[lane] : 0ull;
            #pragma unroll
            for (int off = 8; off; off >>= 1) {
                unsigned long long o = __shfl_down_sync(0xffffffffu, k, off);
                if (o > k) k = o;
            }
            if (lane == 0) {
                unsigned loc = smem_u32(&s_best[rank]);
                s_best[rank] = k;
                #pragma unroll
                for (int d = 0; d < 8; d++)
                    if (d != rank) st_remote_u64(mapa_rank(loc, d), k);
            }
        }
        CLUSTER_SYNC();   // S1: all 8 candidates visible everywhere

        // --- C0: ALL threads compute ti from the 8 candidates -------------
        int ti, w0, shf;
        {
            unsigned long long k = s_best[0];
            #pragma unroll
            for (int d = 1; d < 8; d++) {
                unsigned long long o = s_best[d];
                if (o > k) k = o;
            }
            ti = (int)(0xFFFFFFFFu - (unsigned)(k & 0xFFFFFFFFull));
            w0  = (ti - 127) & ~3;
            shf = (ti - 127) - w0;
        }

        // --- C1: preload own atom's fm window (overlaps warp0's atom scan)
        int a = rank * 16 + wid;
        float* fp = fmr + a * TT;
        float4 fpre[3];
        #pragma unroll
        for (int it = 0; it < 3; it++) {
            int jj4 = lane + 32 * it;
            if (jj4 < 65) {
                int t = w0 + 4 * jj4;
                if (t >= 0 && t + 3 < TT) {
                    fpre[it] = *(const float4*)(fp + t);
                } else {
                    float e0 = (t >= 0 && t < TT)         ? fp[t]     : 0.f;
                    float e1 = (t + 1 >= 0 && t + 1 < TT) ? fp[t + 1] : 0.f;
                    float e2 = (t + 2 >= 0 && t + 2 < TT) ? fp[t + 2] : 0.f;
                    float e3 = (t + 3 >= 0 && t + 3 < TT) ? fp[t + 3] : 0.f;
                    fpre[it] = make_float4(e0, e1, e2, e3);
                }
            }
        }

        // --- C2: warp 0 atom argmax at winning column (gmem, L2-hot) ------
        if (wid == 0) {
            float av = -3.402823466e38f;
            int aarg = 0x7fffffff;
            #pragma unroll
            for (int a4 = 0; a4 < 4; a4++) {
                int aa = lane + 32 * a4;
                float fv = __ldcg(&fmr[aa * TT + ti]);
                if (fv > av) { av = fv; aarg = aa; }
            }
            #pragma unroll
            for (int off = 16; off; off >>= 1) {
                float ov = __shfl_down_sync(0xffffffffu, av, off);
                int   oa = __shfl_down_sync(0xffffffffu, aarg, off);
                if (ov > av || (ov == av && oa < aarg)) { av = ov; aarg = oa; }
            }
            if (lane == 0) {
                sh_v = av; sh_ai = aarg;
                int pa, aa2;
                if (av > 0.f)      { pa = ti; aa2 = aarg; }
                else if (av < 0.f) { pa = (ti == 0) ? 1 : 0; aa2 = (aarg == 0) ? 1 : 0; }
                else               { pa = 0; aa2 = 0; }
                sh_pa = pa; sh_aa = aa2;
            }
        }
        if (tid >= 252) s_w[tid - 252] = 0u;
        __syncthreads();

        float v = sh_v;
        int ai = sh_ai;

        // --- D: rank 0 emb + residual ---
        if (rank == 0 && tid < 128) {
            float e;
            if (tid == 0)      e = (float)sh_pa * (20.f / (float)(TT - 1));
            else if (tid == 1) e = v;
            else               e = atom_emb[sh_aa * EE + (tid - 2)];
            g_emb[(r * NSTEP + step) * 128 + tid] = e;
        } else if (rank == 0 && tid < 256) {
            int k = tid - 128;
            int t = ti - 64 + k;
            if (t >= 0 && t < TT) resr[t] -= v * g_du[ai * KK + k];
        }

        // --- E: window update; xc read from single copy with guards -------
        {
            const float* xp = g_xc + ((long)ai * AA + a) * XCL;
            float*       tp = s_tile + wid * XSTR;
            #pragma unroll
            for (int it = 0; it < 3; it++) {
                int jj4 = lane + 32 * it;
                if (jj4 < 65) {
                    int jp = 4 * jj4;
                    int t = w0 + jp;
                    int jb = jp - shf;
                    float x0 = (jb     >= 0 && jb     < XCL) ? xp[jb]     : 0.f;
                    float x1 = (jb + 1 >= 0 && jb + 1 < XCL) ? xp[jb + 1] : 0.f;
                    float x2 = (jb + 2 >= 0 && jb + 2 < XCL) ? xp[jb + 2] : 0.f;
                    float x3 = (jb + 3 >= 0 && jb + 3 < XCL) ? xp[jb + 3] : 0.f;
                    float4 f = fpre[it];
                    f.x -= v * x0; f.y -= v * x1;
                    f.z -= v * x2; f.w -= v * x3;
                    if (t >= 0 && t + 3 < TT) {
                        *(float4*)(fp + t) = f;
                        *(float4*)(tp + jp) = f;
                    } else {
                        if (t >= 0 && t < TT)         { fp[t]     = f.x; tp[jp]     = f.x; }
                        if (t + 1 >= 0 && t + 1 < TT) { fp[t + 1] = f.y; tp[jp + 1] = f.y; }
                        if (t + 2 >= 0 && t + 2 < TT) { fp[t + 2] = f.z; tp[jp + 2] = f.z; }
                        if (t + 3 >= 0 && t + 3 < TT) { fp[t + 3] = f.w; tp[jp + 3] = f.w; }
                    }
                }
            }
        }
        __syncthreads();

        // --- F: local colmax partial over 16 atoms -> s_w ---
        {
            int c4 = tid & 63, sub = tid >> 6;    // 8 subs x 2 atoms
            #pragma unroll
            for (int pass = 0; pass < 2; pass++) {
                int cc4, ss;
                if (pass == 0) { cc4 = c4; ss = sub; }
                else { if (tid >= 8) break; cc4 = 64; ss = tid; }
                float m0 = -3.402823466e38f, m1 = m0, m2 = m0, m3 = m0;
                #pragma unroll
                for (int i = 0; i < 2; i++) {
                    int aa = ss * 2 + i;
                    float4 xx = *(const float4*)(s_tile + aa * XSTR + 4 * cc4);
                    m0 = fmaxf(m0, xx.x); m1 = fmaxf(m1, xx.y);
                    m2 = fmaxf(m2, xx.z); m3 = fmaxf(m3, xx.w);
                }
                int cb = 4 * cc4;
                atomicMax(&s_w[cb],     fenc(m0));
                atomicMax(&s_w[cb + 1], fenc(m1));
                atomicMax(&s_w[cb + 2], fenc(m2));
                atomicMax(&s_w[cb + 3], fenc(m3));
            }
        }
        __syncthreads();

        // --- G: export partials to the OWNER rank of each window col ---
        if (tid < 260) {
            int t = w0 + tid;
            if (t >= 0 && t < TT) {
                int owner = t >> 11;
                unsigned val = s_w[tid];
                unsigned loc = smem_u32(&s_part[rank * 260 + tid]);
                if (owner == rank) s_part[rank * 260 + tid] = val;
                else st_remote_u32(mapa_rank(loc, owner), val);
            }
        }
        prev_w0 = w0;
        CLUSTER_SYNC();   // S2: partials + fm gmem writes visible
    }

    if (rank != 0) return;   // last cluster op was S2; safe to diverge

    // --- residual norm (rank 0) ---
    float ss = 0.f;
    #pragma unroll
    for (int q = 0; q < 8; q++) {
        float4 vv = ((const float4*)resr)[tid + NTHR * q];
        ss += vv.x * vv.x + vv.y * vv.y + vv.z * vv.z + vv.w * vv.w;
    }
    #pragma unroll
    for (int off = 16; off; off >>= 1)
        ss += __shfl_down_sync(0xffffffffu, ss, off);
    if (lane == 0) s_nred[wid] = ss;
    __syncthreads();
    if (wid == 0) {
        float t2 = (lane < 16) ? s_nred[lane] : 0.f;
        #pragma unroll
        for (int off = 8; off; off >>= 1)
            t2 += __shfl_down_sync(0xffffffffu, t2, off);
        if (lane == 0) g_norm[r] = sqrtf(t2);
    }

    // --- fused final loss: last rank-0 to finish computes it ---
    __threadfence();
    __syncthreads();
    if (tid == 0) s_last = (atomicAdd(&g_done, 1) == NROW - 1);
    __syncthreads();
    if (!s_last) return;
    __threadfence();

    if (tid < 128) s_proj[tid] = proj[tid];
    __syncthreads();

    // keys: 16 warps x 4 keys (8 lanes per key)
    {
        int key = wid * 4 + (lane >> 3);
        int sl = lane & 7;
        const float* e = g_emb + key * 128;
        float p = 0.f;
        #pragma unroll
        for (int q = 0; q < 16; q++) {
            int j = sl + 8 * q;
            p += e[j] * s_proj[j];
        }
        #pragma unroll
        for (int off = 1; off < 8; off <<= 1)
            p += __shfl_xor_sync(0xffffffffu, p, off);
        if (sl == 0) s_keys[key] = p;
    }
    __syncthreads();

    if (tid < 4) {   // stable insertion sort, ascending (matches jnp.argsort)
        int ord[16];
        for (int i = 0; i < 16; i++) ord[i] = i;
        for (int i = 1; i < 16; i++) {
            int oi = ord[i];
            float ki = s_keys[tid * 16 + oi];
            int j = i - 1;
            while (j >= 0 && s_keys[tid * 16 + ord[j]] > ki) { ord[j + 1] = ord[j]; j--; }
            ord[j + 1] = oi;
        }
        for (int i = 0; i < 16; i++) s_order[tid * 16 + i] = ord[i];
    }
    __syncthreads();

    float acc = 0.f;
    #pragma unroll
    for (int q = 0; q < 8; q++) {
        int i = tid + NTHR * q;
        int bb = i >> 11;
        int st = (i >> 7) & 15;
        int e = i & 127;
        int sa = s_order[bb * 16 + st];
        int sb = s_order[(2 + bb) * 16 + st];
        float dd = g_emb[(bb * 16 + sa) * 128 + e] - g_emb[((2 + bb) * 16 + sb) * 128 + e];
        acc += dd * dd;
    }
    #pragma unroll
    for (int off = 16; off; off >>= 1)
        acc += __shfl_down_sync(0xffffffffu, acc, off);
    if (lane == 0) s_nred[wid] = acc;
    __syncthreads();
    if (tid == 0) {
        float t2 = 0.f;
        for (int w = 0; w < 16; w++) t2 += s_nred[w];
        out[0] = t2 / 4096.f
               + 0.5f * (fabsf(g_norm[0] - g_norm[2]) + fabsf(g_norm[1] - g_norm[3]));
    }
}

// ---------------- launch ----------------------------------------------------
extern "C" void kernel_launch(void* const* d_in, const int* in_sizes, int n_in,
                              void* d_out, int out_size)
{
    (void)in_sizes; (void)n_in; (void)out_size;
    const float* a    = (const float*)d_in[0];
    const float* b    = (const float*)d_in[1];
    const float* d    = (const float*)d_in[2];
    const float* aemb = (const float*)d_in[3];
    const float* proj = (const float*)d_in[4];
    float* out = (float*)d_out;

    cudaFuncSetAttribute(steps_kernel,
                         cudaFuncAttributeMaxDynamicSharedMemorySize, SMEM_STEPS);

    prep_kernel<<<384, 128>>>(a, b, d);
    corr_kernel<<<512, 256>>>(1);     // xcorr -> g_xc (single copy)
    corr_kernel<<<1024, 256>>>(0);    // fm -> g_fm + g_cm
    steps_kernel<<<NROW * CLUSTER, NTHR, SMEM_STEPS>>>(aemb, proj, out);
}